// round 1
// baseline (speedup 1.0000x reference)
#include <cuda_runtime.h>
#include <cstdint>

// CIN (xDeepFM) fused 3-layer kernel, fp32 SIMT baseline.
// B=2048, F0=39, D=32, LAYER_SIZE=[200,200,200], SPLIT_HALF.
//
// Per (b,d): cur_i[o] = relu( sum_{m<39, n<nf_i} x[m]*h[n]*W_i[m*nf_i+n, o] + b_i[o] )
//   layer0: h = x (nf=39);  layers 1,2: h = prev hidden (nf=100)
//   layers 0,1: hidden = cur[0:100], direct = cur[100:200]; layer 2: direct = cur
// out[b, ch] = sum_d concat(direct0, direct1, direct2)[ch]

#define F0C 39
#define DD 32
#define SS 200
#define NFH 100
#define OPW 24
#define NTHREADS 256

#define SMEM_FLOATS (2 * NFH * SS + F0C * DD + NFH * DD)   // 44448
#define SMEM_BYTES (SMEM_FLOATS * 4)                        // 177792

__device__ __forceinline__ void cp_async16(uint32_t saddr, const void* gptr) {
    asm volatile("cp.async.cg.shared.global [%0], [%1], 16;\n"
                 :: "r"(saddr), "l"(gptr) : "memory");
}
__device__ __forceinline__ void cp_commit() {
    asm volatile("cp.async.commit_group;\n" ::: "memory");
}
template <int N>
__device__ __forceinline__ void cp_wait() {
    asm volatile("cp.async.wait_group %0;\n" :: "n"(N) : "memory");
}

// One CIN layer for this CTA's b. NF = fields of current hidden (39 or 100).
// K = F0C * NF, walked as F0C chunks of NF rows; W chunk double-buffered in smem.
template <int NF>
__device__ __forceinline__ void run_layer(
    const float* __restrict__ Wg, const float* __restrict__ bg,
    float* Wbuf0, float* Wbuf1,
    const float* xsrc, const float* hsrc,
    float* hdst,            // nullptr on last layer
    float* outb, int Lmode, // 0,1,2
    int tid, int w, int d, int o0, int oX)
{
    const int chunk_f4 = NF * SS / 4;
    uint32_t sb0 = (uint32_t)__cvta_generic_to_shared(Wbuf0);
    uint32_t sb1 = (uint32_t)__cvta_generic_to_shared(Wbuf1);

    // prefetch chunk m=0
    {
        const float4* g = (const float4*)Wg;
        for (int i = tid; i < chunk_f4; i += NTHREADS)
            cp_async16(sb0 + 16u * (uint32_t)i, g + i);
        cp_commit();
    }

    float acc[25];
#pragma unroll
    for (int j = 0; j < 25; j++) acc[j] = 0.f;

    for (int m = 0; m < F0C; m++) {
        if (m + 1 < F0C) {
            uint32_t sb = ((m + 1) & 1) ? sb1 : sb0;
            const float4* g = (const float4*)(Wg + (size_t)(m + 1) * NF * SS);
            for (int i = tid; i < chunk_f4; i += NTHREADS)
                cp_async16(sb + 16u * (uint32_t)i, g + i);
            cp_commit();
            cp_wait<1>();   // chunk m has landed
        } else {
            cp_wait<0>();
        }
        __syncthreads();

        const float* Wb = (m & 1) ? Wbuf1 : Wbuf0;
        const float xm = xsrc[m * DD + d];
        const float* Wo = Wb + o0;
#pragma unroll 2
        for (int n = 0; n < NF; n++) {
            float a = xm * hsrc[n * DD + d];
            const float4* Wv = (const float4*)(Wo + n * SS);
#pragma unroll
            for (int q = 0; q < 6; q++) {
                float4 wq = Wv[q];
                acc[4 * q + 0] += a * wq.x;
                acc[4 * q + 1] += a * wq.y;
                acc[4 * q + 2] += a * wq.z;
                acc[4 * q + 3] += a * wq.w;
            }
            acc[24] += a * Wb[n * SS + oX];
        }
        __syncthreads();   // before buffer (m&1) gets overwritten by prefetch m+2
    }

    // epilogue: bias + relu, hidden writeback, d-reduction of direct part
#pragma unroll
    for (int j = 0; j < 25; j++) {
        int o = (j < OPW) ? (o0 + j) : oX;
        float v = fmaxf(acc[j] + __ldg(bg + o), 0.f);
        if (hdst != nullptr && o < NFH) hdst[o * DD + d] = v;
        bool is_direct = (Lmode == 2) || (o >= NFH);
        float r = is_direct ? v : 0.f;
        r += __shfl_xor_sync(0xffffffffu, r, 16);
        r += __shfl_xor_sync(0xffffffffu, r, 8);
        r += __shfl_xor_sync(0xffffffffu, r, 4);
        r += __shfl_xor_sync(0xffffffffu, r, 2);
        r += __shfl_xor_sync(0xffffffffu, r, 1);
        if (is_direct && d == 0) {
            int ch = (Lmode == 0) ? (o - NFH) : (Lmode == 1) ? o : (SS + o);
            outb[ch] = r;
        }
    }
    __syncthreads();   // hidden visible + W buffers free before next layer
}

__global__ void __launch_bounds__(NTHREADS, 1)
cin_kernel(const float* __restrict__ x,
           const float* __restrict__ W0, const float* __restrict__ W1,
           const float* __restrict__ W2,
           const float* __restrict__ b0, const float* __restrict__ b1,
           const float* __restrict__ b2,
           float* __restrict__ out)
{
    extern __shared__ float smem[];
    float* Wbuf0 = smem;
    float* Wbuf1 = smem + NFH * SS;
    float* xs = smem + 2 * NFH * SS;     // [39][32]
    float* hs = xs + F0C * DD;           // [100][32]

    const int tid = threadIdx.x;
    const int w = tid >> 5;
    const int d = tid & 31;
    const int o0 = w * OPW;              // 24*w (16B aligned in W rows)
    const int oX = 8 * OPW + w;          // 192 + w
    const int b = blockIdx.x;

    // stage x[b] : 39*32 floats
    {
        const float4* src = (const float4*)(x + (size_t)b * (F0C * DD));
        float4* dst = (float4*)xs;
        for (int i = tid; i < F0C * DD / 4; i += NTHREADS) dst[i] = src[i];
    }
    __syncthreads();

    float* outb = out + (size_t)b * (2 * SS);   // 400 channels per b

    run_layer<F0C>(W0, b0, Wbuf0, Wbuf1, xs, xs, hs, outb, 0, tid, w, d, o0, oX);
    run_layer<NFH>(W1, b1, Wbuf0, Wbuf1, xs, hs, hs, outb, 1, tid, w, d, o0, oX);
    run_layer<NFH>(W2, b2, Wbuf0, Wbuf1, xs, hs, nullptr, outb, 2, tid, w, d, o0, oX);
}

extern "C" void kernel_launch(void* const* d_in, const int* in_sizes, int n_in,
                              void* d_out, int out_size)
{
    // Identify inputs by element count (robust to metadata ordering):
    //   x: B*39*32, W0: 1521*200=304200, W1/W2: 3900*200=780000 (in order),
    //   b0/b1/b2: 200 (in order).
    const float* x = nullptr;
    const float* W0 = nullptr;
    const float* W1 = nullptr;
    const float* W2 = nullptr;
    const float* bb[3] = {nullptr, nullptr, nullptr};
    int nb = 0;
    long xsz = 0;

    for (int i = 0; i < n_in; i++) {
        long sz = in_sizes[i];
        const float* p = (const float*)d_in[i];
        if (sz == 1521L * 200) {
            W0 = p;
        } else if (sz == 3900L * 200) {
            if (!W1) W1 = p; else W2 = p;
        } else if (sz == 200) {
            if (nb < 3) bb[nb++] = p;
        } else {
            x = p; xsz = sz;
        }
    }

    int B = (int)(xsz / (F0C * DD));

    cudaFuncSetAttribute(cin_kernel,
                         cudaFuncAttributeMaxDynamicSharedMemorySize, SMEM_BYTES);
    cin_kernel<<<B, NTHREADS, SMEM_BYTES>>>(x, W0, W1, W2,
                                            bb[0], bb[1], bb[2],
                                            (float*)d_out);
}

// round 2
// speedup vs baseline: 1.0004x; 1.0004x over previous
#include <cuda_runtime.h>
#include <cstdint>

// CIN (xDeepFM) fused 3-layer kernel, fp32 SIMT baseline.
// B=2048, F0=39, D=32, LAYER_SIZE=[200,200,200], SPLIT_HALF.
//
// Per (b,d): cur_i[o] = relu( sum_{m<39, n<nf_i} x[m]*h[n]*W_i[m*nf_i+n, o] + b_i[o] )
//   layer0: h = x (nf=39);  layers 1,2: h = prev hidden (nf=100)
//   layers 0,1: hidden = cur[0:100], direct = cur[100:200]; layer 2: direct = cur
// out[b, ch] = sum_d concat(direct0, direct1, direct2)[ch]

#define F0C 39
#define DD 32
#define SS 200
#define NFH 100
#define OPW 24
#define NTHREADS 256

#define SMEM_FLOATS (2 * NFH * SS + F0C * DD + NFH * DD)   // 44448
#define SMEM_BYTES (SMEM_FLOATS * 4)                        // 177792

__device__ __forceinline__ void cp_async16(uint32_t saddr, const void* gptr) {
    asm volatile("cp.async.cg.shared.global [%0], [%1], 16;\n"
                 :: "r"(saddr), "l"(gptr) : "memory");
}
__device__ __forceinline__ void cp_commit() {
    asm volatile("cp.async.commit_group;\n" ::: "memory");
}
template <int N>
__device__ __forceinline__ void cp_wait() {
    asm volatile("cp.async.wait_group %0;\n" :: "n"(N) : "memory");
}

// One CIN layer for this CTA's b. NF = fields of current hidden (39 or 100).
// K = F0C * NF, walked as F0C chunks of NF rows; W chunk double-buffered in smem.
template <int NF>
__device__ __forceinline__ void run_layer(
    const float* __restrict__ Wg, const float* __restrict__ bg,
    float* Wbuf0, float* Wbuf1,
    const float* xsrc, const float* hsrc,
    float* hdst,            // nullptr on last layer
    float* outb, int Lmode, // 0,1,2
    int tid, int w, int d, int o0, int oX)
{
    const int chunk_f4 = NF * SS / 4;
    uint32_t sb0 = (uint32_t)__cvta_generic_to_shared(Wbuf0);
    uint32_t sb1 = (uint32_t)__cvta_generic_to_shared(Wbuf1);

    // prefetch chunk m=0
    {
        const float4* g = (const float4*)Wg;
        for (int i = tid; i < chunk_f4; i += NTHREADS)
            cp_async16(sb0 + 16u * (uint32_t)i, g + i);
        cp_commit();
    }

    float acc[25];
#pragma unroll
    for (int j = 0; j < 25; j++) acc[j] = 0.f;

    for (int m = 0; m < F0C; m++) {
        if (m + 1 < F0C) {
            uint32_t sb = ((m + 1) & 1) ? sb1 : sb0;
            const float4* g = (const float4*)(Wg + (size_t)(m + 1) * NF * SS);
            for (int i = tid; i < chunk_f4; i += NTHREADS)
                cp_async16(sb + 16u * (uint32_t)i, g + i);
            cp_commit();
            cp_wait<1>();   // chunk m has landed
        } else {
            cp_wait<0>();
        }
        __syncthreads();

        const float* Wb = (m & 1) ? Wbuf1 : Wbuf0;
        const float xm = xsrc[m * DD + d];
        const float* Wo = Wb + o0;
#pragma unroll 2
        for (int n = 0; n < NF; n++) {
            float a = xm * hsrc[n * DD + d];
            const float4* Wv = (const float4*)(Wo + n * SS);
#pragma unroll
            for (int q = 0; q < 6; q++) {
                float4 wq = Wv[q];
                acc[4 * q + 0] += a * wq.x;
                acc[4 * q + 1] += a * wq.y;
                acc[4 * q + 2] += a * wq.z;
                acc[4 * q + 3] += a * wq.w;
            }
            acc[24] += a * Wb[n * SS + oX];
        }
        __syncthreads();   // before buffer (m&1) gets overwritten by prefetch m+2
    }

    // epilogue: bias + relu, hidden writeback, d-reduction of direct part
#pragma unroll
    for (int j = 0; j < 25; j++) {
        int o = (j < OPW) ? (o0 + j) : oX;
        float v = fmaxf(acc[j] + __ldg(bg + o), 0.f);
        if (hdst != nullptr && o < NFH) hdst[o * DD + d] = v;
        bool is_direct = (Lmode == 2) || (o >= NFH);
        float r = is_direct ? v : 0.f;
        r += __shfl_xor_sync(0xffffffffu, r, 16);
        r += __shfl_xor_sync(0xffffffffu, r, 8);
        r += __shfl_xor_sync(0xffffffffu, r, 4);
        r += __shfl_xor_sync(0xffffffffu, r, 2);
        r += __shfl_xor_sync(0xffffffffu, r, 1);
        if (is_direct && d == 0) {
            int ch = (Lmode == 0) ? (o - NFH) : (Lmode == 1) ? o : (SS + o);
            outb[ch] = r;
        }
    }
    __syncthreads();   // hidden visible + W buffers free before next layer
}

__global__ void __launch_bounds__(NTHREADS, 1)
cin_kernel(const float* __restrict__ x,
           const float* __restrict__ W0, const float* __restrict__ W1,
           const float* __restrict__ W2,
           const float* __restrict__ b0, const float* __restrict__ b1,
           const float* __restrict__ b2,
           float* __restrict__ out)
{
    extern __shared__ float smem[];
    float* Wbuf0 = smem;
    float* Wbuf1 = smem + NFH * SS;
    float* xs = smem + 2 * NFH * SS;     // [39][32]
    float* hs = xs + F0C * DD;           // [100][32]

    const int tid = threadIdx.x;
    const int w = tid >> 5;
    const int d = tid & 31;
    const int o0 = w * OPW;              // 24*w (16B aligned in W rows)
    const int oX = 8 * OPW + w;          // 192 + w
    const int b = blockIdx.x;

    // stage x[b] : 39*32 floats
    {
        const float4* src = (const float4*)(x + (size_t)b * (F0C * DD));
        float4* dst = (float4*)xs;
        for (int i = tid; i < F0C * DD / 4; i += NTHREADS) dst[i] = src[i];
    }
    __syncthreads();

    float* outb = out + (size_t)b * (2 * SS);   // 400 channels per b

    run_layer<F0C>(W0, b0, Wbuf0, Wbuf1, xs, xs, hs, outb, 0, tid, w, d, o0, oX);
    run_layer<NFH>(W1, b1, Wbuf0, Wbuf1, xs, hs, hs, outb, 1, tid, w, d, o0, oX);
    run_layer<NFH>(W2, b2, Wbuf0, Wbuf1, xs, hs, nullptr, outb, 2, tid, w, d, o0, oX);
}

extern "C" void kernel_launch(void* const* d_in, const int* in_sizes, int n_in,
                              void* d_out, int out_size)
{
    // Identify inputs by element count (robust to metadata ordering):
    //   x: B*39*32, W0: 1521*200=304200, W1/W2: 3900*200=780000 (in order),
    //   b0/b1/b2: 200 (in order).
    const float* x = nullptr;
    const float* W0 = nullptr;
    const float* W1 = nullptr;
    const float* W2 = nullptr;
    const float* bb[3] = {nullptr, nullptr, nullptr};
    int nb = 0;
    long xsz = 0;

    for (int i = 0; i < n_in; i++) {
        long sz = in_sizes[i];
        const float* p = (const float*)d_in[i];
        if (sz == 1521L * 200) {
            W0 = p;
        } else if (sz == 3900L * 200) {
            if (!W1) W1 = p; else W2 = p;
        } else if (sz == 200) {
            if (nb < 3) bb[nb++] = p;
        } else {
            x = p; xsz = sz;
        }
    }

    int B = (int)(xsz / (F0C * DD));

    cudaFuncSetAttribute(cin_kernel,
                         cudaFuncAttributeMaxDynamicSharedMemorySize, SMEM_BYTES);
    cin_kernel<<<B, NTHREADS, SMEM_BYTES>>>(x, W0, W1, W2,
                                            bb[0], bb[1], bb[2],
                                            (float*)d_out);
}

// round 4
// speedup vs baseline: 2.9002x; 2.8989x over previous
#include <cuda_runtime.h>
#include <cstdint>

#define F0C 39
#define DD 32
#define SS 200
#define NFH 100
#define NPAD 208
#define K0 1521
#define T0 96
#define K12 3900
#define T12 244

#define ASPLIT 4096
#define ABUF   8192
#define BSPLIT 6656
#define BBLK   13312
#define IMG0_BYTES (T0 * BBLK)
#define IMG12_BYTES (T12 * BBLK)

#define SM_BIAS 0
#define SM_X    2432
#define SM_H    22400
#define SM_A    73600
#define SM_B    89984
#define SMEM_TOTAL 143232

__device__ __align__(16) unsigned char g_wimg[IMG0_BYTES + 2 * IMG12_BYTES];

__device__ __forceinline__ void cp_async16(uint32_t s, const void* g) {
    asm volatile("cp.async.cg.shared.global [%0], [%1], 16;\n" :: "r"(s), "l"(g) : "memory");
}
__device__ __forceinline__ void cp_commit() { asm volatile("cp.async.commit_group;\n" ::: "memory"); }
template <int N> __device__ __forceinline__ void cp_wait() {
    asm volatile("cp.async.wait_group %0;\n" :: "n"(N) : "memory");
}
__device__ __forceinline__ uint32_t cvt2(float lo, float hi) {
    uint32_t r;
    asm("cvt.rn.bf16x2.f32 %0, %1, %2;" : "=r"(r) : "f"(hi), "f"(lo));
    return r;
}
__device__ __forceinline__ void split2(float p0, float p1, uint32_t& hp, uint32_t& lp) {
    hp = cvt2(p0, p1);
    lp = cvt2(p0 - __uint_as_float(hp << 16), p1 - __uint_as_float(hp & 0xffff0000u));
}
__device__ __forceinline__ void ldsm4(uint32_t* r, uint32_t a) {
    asm volatile("ldmatrix.sync.aligned.m8n8.x4.shared.b16 {%0,%1,%2,%3}, [%4];"
                 : "=r"(r[0]), "=r"(r[1]), "=r"(r[2]), "=r"(r[3]) : "r"(a));
}
__device__ __forceinline__ void ldsm2(uint32_t* r, uint32_t a) {
    asm volatile("ldmatrix.sync.aligned.m8n8.x2.shared.b16 {%0,%1}, [%2];"
                 : "=r"(r[0]), "=r"(r[1]) : "r"(a));
}
#define MMA(D, A, B0, B1)                                                     \
    asm volatile("mma.sync.aligned.m16n8k16.row.col.f32.bf16.bf16.f32 "       \
                 "{%0,%1,%2,%3}, {%4,%5,%6,%7}, {%8,%9}, {%0,%1,%2,%3};"      \
                 : "+f"(D[0]), "+f"(D[1]), "+f"(D[2]), "+f"(D[3])             \
                 : "r"((A)[0]), "r"((A)[1]), "r"((A)[2]), "r"((A)[3]),        \
                   "r"(B0), "r"(B1))

// ---- prep: W[K,200] -> tile-packed bf16 hi/lo images (8x8 mats, n-major) ----
__global__ void prep_kernel(const float* __restrict__ W, int K, int T, int which)
{
    unsigned char* img = g_wimg +
        ((which == 0) ? 0 : (which == 1) ? IMG0_BYTES : (IMG0_BYTES + IMG12_BYTES));
    int idx = blockIdx.x * 256 + threadIdx.x;
    if (idx >= T * 8 * NPAD) return;
    int o = idx % NPAD;
    int r = idx / NPAD;
    int p = r & 7, t = r >> 3;
    int c0 = t * 16 + 2 * p;
    float v0 = (o < SS && c0 < K) ? W[(size_t)c0 * SS + o] : 0.f;
    float v1 = (o < SS && c0 + 1 < K) ? W[(size_t)(c0 + 1) * SS + o] : 0.f;
    uint32_t hp, lp;
    split2(v0, v1, hp, lp);
    int nt = o >> 3, nr = o & 7, ks = p >> 2, j = p & 3;
    size_t off = (size_t)t * BBLK + (nt * 2 + ks) * 128 + nr * 16 + j * 4;
    *(uint32_t*)(img + off) = hp;
    *(uint32_t*)(img + off + BSPLIT) = lp;
}

// ---- main ----
__device__ __forceinline__ void prefetchB(const unsigned char* img, int t, int T,
                                          uint32_t sb, int tid)
{
    if (t < T) {
        const unsigned char* src = img + (size_t)t * BBLK;
        uint32_t dst = sb + SM_B + (uint32_t)(t & 3) * (uint32_t)BBLK;
        for (int i = tid; i < BBLK / 16; i += 256)
            cp_async16(dst + 16u * (uint32_t)i, src + 16 * i);
    }
    cp_commit();
}

// Build A (z products) as packed 8x8 mats, bf16 hi/lo. 256 threads, 1 row-half each.
template <int NF>
__device__ __forceinline__ void stageA(int t, int K, const float* xs, const float* h,
                                       char* abuf, int tid)
{
    int r = tid & 127;
    int kh = tid >> 7;
    int bl = r >> 5, d = r & 31;
    const float* xb = xs + bl * F0C * DD + d;
    const float* hb = h + bl * NF * DD + d;
    int cb = t * 16 + kh * 8;
    uint32_t hp[4], lp[4];
#pragma unroll
    for (int j = 0; j < 4; j++) {
        int c0 = cb + 2 * j;
        float p0 = 0.f, p1 = 0.f;
        if (c0 < K)     p0 = xb[(c0 / NF) * DD] * hb[(c0 % NF) * DD];
        if (c0 + 1 < K) p1 = xb[((c0 + 1) / NF) * DD] * hb[((c0 + 1) % NF) * DD];
        split2(p0, p1, hp[j], lp[j]);
    }
    uint32_t off = (uint32_t)((((r >> 3) * 2 + kh) << 7) + (r & 7) * 16);
    *(uint4*)(abuf + off) = *(uint4*)hp;
    *(uint4*)(abuf + ASPLIT + off) = *(uint4*)lp;
}

template <int NF, int LMODE>
__device__ void run_layer(const unsigned char* img, int T, int K,
                          const float* xs, const float* hsrc, float* hs,
                          const float* bias, float* out,
                          char* smem, uint32_t sb, int bbase, int Btot)
{
    const int tid = threadIdx.x;
    const int w = tid >> 5, lane = tid & 31;
    const int mq = w >> 1, nh = w & 1;

    float acc[2][13][4];
#pragma unroll
    for (int mt = 0; mt < 2; mt++)
#pragma unroll
        for (int nt = 0; nt < 13; nt++)
#pragma unroll
            for (int q = 0; q < 4; q++) acc[mt][nt][q] = 0.f;

    // prologue (caller guarantees a preceding __syncthreads)
    prefetchB(img, 0, T, sb, tid);
    prefetchB(img, 1, T, sb, tid);
    prefetchB(img, 2, T, sb, tid);
    stageA<NF>(0, K, xs, hsrc, smem + SM_A, tid);

    const uint32_t aoff = ((lane >> 3) & 1) * 256u + ((lane >> 3) >> 1) * 128u + (lane & 7) * 16u;
    const uint32_t boff = (uint32_t)lane * 16u;
    const uint32_t boff2 = (uint32_t)(lane & 15) * 16u;

    for (int t = 0; t < T; t++) {
        cp_wait<2>();
        __syncthreads();
        prefetchB(img, t + 3, T, sb, tid);

        uint32_t ab = sb + SM_A + (uint32_t)(t & 1) * ABUF + (uint32_t)mq * 1024u;
        uint32_t ah[2][4], al[2][4];
        ldsm4(ah[0], ab + aoff);
        ldsm4(ah[1], ab + 512u + aoff);
        ldsm4(al[0], ab + ASPLIT + aoff);
        ldsm4(al[1], ab + ASPLIT + 512u + aoff);

        uint32_t bb = sb + SM_B + (uint32_t)(t & 3) * (uint32_t)BBLK + (uint32_t)nh * 3328u;
#pragma unroll
        for (int i = 0; i < 6; i++) {
            uint32_t bh[4], bl4[4];
            ldsm4(bh, bb + i * 512u + boff);
            ldsm4(bl4, bb + BSPLIT + i * 512u + boff);
#pragma unroll
            for (int mt = 0; mt < 2; mt++) {
                MMA(acc[mt][2 * i], ah[mt], bh[0], bh[1]);
                MMA(acc[mt][2 * i], ah[mt], bl4[0], bl4[1]);
                MMA(acc[mt][2 * i], al[mt], bh[0], bh[1]);
                MMA(acc[mt][2 * i + 1], ah[mt], bh[2], bh[3]);
                MMA(acc[mt][2 * i + 1], ah[mt], bl4[2], bl4[3]);
                MMA(acc[mt][2 * i + 1], al[mt], bh[2], bh[3]);
            }
        }
        {
            uint32_t bh2[2], bl2[2];
            ldsm2(bh2, bb + 12 * 256u + boff2);
            ldsm2(bl2, bb + BSPLIT + 12 * 256u + boff2);
#pragma unroll
            for (int mt = 0; mt < 2; mt++) {
                MMA(acc[mt][12], ah[mt], bh2[0], bh2[1]);
                MMA(acc[mt][12], ah[mt], bl2[0], bl2[1]);
                MMA(acc[mt][12], al[mt], bh2[0], bh2[1]);
            }
        }
        if (t + 1 < T)
            stageA<NF>(t + 1, K, xs, hsrc, smem + SM_A + ((t + 1) & 1) * ABUF, tid);
    }
    cp_wait<0>();

    // ---- epilogue ----
    int b = bbase + mq;
    bool bok = b < Btot;
    float* outp = out + (size_t)b * (2 * SS);
    const float* bi = bias + LMODE * SS;
    int quad = lane & 3, ldq = lane >> 2;
#pragma unroll
    for (int nt = 0; nt < 13; nt++) {
        int oe = nh * 104 + nt * 8 + 2 * quad;
        float be = bi[oe], bo = bi[oe + 1];
        float se = 0.f, so = 0.f;
#pragma unroll
        for (int mt = 0; mt < 2; mt++) {
            float v0 = fmaxf(acc[mt][nt][0] + be, 0.f);
            float v1 = fmaxf(acc[mt][nt][1] + bo, 0.f);
            float v2 = fmaxf(acc[mt][nt][2] + be, 0.f);
            float v3 = fmaxf(acc[mt][nt][3] + bo, 0.f);
            if (LMODE < 2 && bok) {
                int d0 = mt * 16 + ldq;
                if (oe < NFH) {
                    hs[(mq * NFH + oe) * DD + d0] = v0;
                    hs[(mq * NFH + oe) * DD + d0 + 8] = v2;
                }
                if (oe + 1 < NFH) {
                    hs[(mq * NFH + oe + 1) * DD + d0] = v1;
                    hs[(mq * NFH + oe + 1) * DD + d0 + 8] = v3;
                }
            }
            se += v0 + v2;
            so += v1 + v3;
        }
        se += __shfl_xor_sync(0xffffffffu, se, 4);
        se += __shfl_xor_sync(0xffffffffu, se, 8);
        se += __shfl_xor_sync(0xffffffffu, se, 16);
        so += __shfl_xor_sync(0xffffffffu, so, 4);
        so += __shfl_xor_sync(0xffffffffu, so, 8);
        so += __shfl_xor_sync(0xffffffffu, so, 16);
        if (ldq == 0 && bok) {
            bool de = (LMODE == 2) ? (oe < SS) : (oe >= NFH && oe < SS);
            bool dd = (LMODE == 2) ? (oe + 1 < SS) : (oe + 1 >= NFH && oe + 1 < SS);
            int che = (LMODE == 0) ? (oe - NFH) : (LMODE == 1) ? oe : (SS + oe);
            int cho = che + 1;
            if (de) outp[che] = se;
            if (dd) outp[cho] = so;
        }
    }
    __syncthreads();
}

__global__ void __launch_bounds__(256, 1)
cin_main(const float* __restrict__ x,
         const float* __restrict__ b0g, const float* __restrict__ b1g,
         const float* __restrict__ b2g,
         float* __restrict__ out, int Btot)
{
    extern __shared__ char smem[];
    uint32_t sb = (uint32_t)__cvta_generic_to_shared(smem);
    int tid = threadIdx.x;

    float* bias = (float*)(smem + SM_BIAS);
    for (int i = tid; i < 3 * SS; i += 256)
        bias[i] = (i < SS) ? b0g[i] : (i < 2 * SS) ? b1g[i - SS] : b2g[i - 2 * SS];

    float* xs = (float*)(smem + SM_X);
    float* hs = (float*)(smem + SM_H);
    int bbase = blockIdx.x * 4;
    for (int bl = 0; bl < 4; bl++) {
        int b = bbase + bl;
        float4* dst = (float4*)(xs + bl * F0C * DD);
        if (b < Btot) {
            const float4* src = (const float4*)(x + (size_t)b * (F0C * DD));
            for (int i = tid; i < F0C * DD / 4; i += 256) dst[i] = src[i];
        } else {
            float4 z = make_float4(0.f, 0.f, 0.f, 0.f);
            for (int i = tid; i < F0C * DD / 4; i += 256) dst[i] = z;
        }
    }
    __syncthreads();

    run_layer<F0C, 0>(g_wimg, T0, K0, xs, xs, hs, bias, out, smem, sb, bbase, Btot);
    run_layer<NFH, 1>(g_wimg + IMG0_BYTES, T12, K12, xs, hs, hs, bias, out, smem, sb, bbase, Btot);
    run_layer<NFH, 2>(g_wimg + IMG0_BYTES + IMG12_BYTES, T12, K12, xs, hs, hs, bias, out, smem, sb, bbase, Btot);
}

extern "C" void kernel_launch(void* const* d_in, const int* in_sizes, int n_in,
                              void* d_out, int out_size)
{
    const float* x = nullptr;
    const float* W0 = nullptr;
    const float* W1 = nullptr;
    const float* W2 = nullptr;
    const float* bb[3] = {nullptr, nullptr, nullptr};
    int nb = 0;
    long xsz = 0;

    for (int i = 0; i < n_in; i++) {
        long sz = in_sizes[i];
        const float* p = (const float*)d_in[i];
        if (sz == (long)K0 * SS) W0 = p;
        else if (sz == (long)K12 * SS) { if (!W1) W1 = p; else W2 = p; }
        else if (sz == SS) { if (nb < 3) bb[nb++] = p; }
        else { x = p; xsz = sz; }
    }

    int B = (int)(xsz / (F0C * DD));

    int n0 = T0 * 8 * NPAD, n12 = T12 * 8 * NPAD;
    prep_kernel<<<(n0 + 255) / 256, 256>>>(W0, K0, T0, 0);
    prep_kernel<<<(n12 + 255) / 256, 256>>>(W1, K12, T12, 1);
    prep_kernel<<<(n12 + 255) / 256, 256>>>(W2, K12, T12, 2);

    cudaFuncSetAttribute(cin_main, cudaFuncAttributeMaxDynamicSharedMemorySize, SMEM_TOTAL);
    cin_main<<<(B + 3) / 4, 256, SMEM_TOTAL>>>(x, bb[0], bb[1], bb[2], (float*)d_out, B);
}

// round 5
// speedup vs baseline: 3.0051x; 1.0362x over previous
#include <cuda_runtime.h>
#include <cstdint>

#define F0C 39
#define DD 32
#define SS 200
#define NFH 100
#define NPAD 208
#define K0 1521
#define T0 96
#define K12 3900
#define T12 244

#define ASPLIT 4096
#define ABUF   8192
#define BSPLIT 6656
#define BBLK   13312
#define IMG0_BYTES (T0 * BBLK)
#define IMG12_BYTES (T12 * BBLK)

#define SM_BIAS 0
#define SM_X    2432
#define SM_H    22400
#define SM_A    73600
#define SM_B    89984
#define SMEM_TOTAL 143232

#define NT 512

__device__ __align__(16) unsigned char g_wimg[IMG0_BYTES + 2 * IMG12_BYTES];

__device__ __forceinline__ void cp_async16(uint32_t s, const void* g) {
    asm volatile("cp.async.cg.shared.global [%0], [%1], 16;\n" :: "r"(s), "l"(g) : "memory");
}
__device__ __forceinline__ void cp_commit() { asm volatile("cp.async.commit_group;\n" ::: "memory"); }
template <int N> __device__ __forceinline__ void cp_wait() {
    asm volatile("cp.async.wait_group %0;\n" :: "n"(N) : "memory");
}
__device__ __forceinline__ uint32_t cvt2(float lo, float hi) {
    uint32_t r;
    asm("cvt.rn.bf16x2.f32 %0, %1, %2;" : "=r"(r) : "f"(hi), "f"(lo));
    return r;
}
__device__ __forceinline__ void split2(float p0, float p1, uint32_t& hp, uint32_t& lp) {
    hp = cvt2(p0, p1);
    lp = cvt2(p0 - __uint_as_float(hp << 16), p1 - __uint_as_float(hp & 0xffff0000u));
}
__device__ __forceinline__ void ldsm4(uint32_t* r, uint32_t a) {
    asm volatile("ldmatrix.sync.aligned.m8n8.x4.shared.b16 {%0,%1,%2,%3}, [%4];"
                 : "=r"(r[0]), "=r"(r[1]), "=r"(r[2]), "=r"(r[3]) : "r"(a));
}
__device__ __forceinline__ void ldsm2(uint32_t* r, uint32_t a) {
    asm volatile("ldmatrix.sync.aligned.m8n8.x2.shared.b16 {%0,%1}, [%2];"
                 : "=r"(r[0]), "=r"(r[1]) : "r"(a));
}
#define MMA(D, A, B0, B1)                                                     \
    asm volatile("mma.sync.aligned.m16n8k16.row.col.f32.bf16.bf16.f32 "       \
                 "{%0,%1,%2,%3}, {%4,%5,%6,%7}, {%8,%9}, {%0,%1,%2,%3};"      \
                 : "+f"(D[0]), "+f"(D[1]), "+f"(D[2]), "+f"(D[3])             \
                 : "r"((A)[0]), "r"((A)[1]), "r"((A)[2]), "r"((A)[3]),        \
                   "r"(B0), "r"(B1))

// ---- prep: W[K,200] -> tile-packed bf16 hi/lo images (8x8 mats, n-major) ----
__global__ void prep_kernel(const float* __restrict__ W, int K, int T, int which)
{
    unsigned char* img = g_wimg +
        ((which == 0) ? 0 : (which == 1) ? IMG0_BYTES : (IMG0_BYTES + IMG12_BYTES));
    int idx = blockIdx.x * 256 + threadIdx.x;
    if (idx >= T * 8 * NPAD) return;
    int o = idx % NPAD;
    int r = idx / NPAD;
    int p = r & 7, t = r >> 3;
    int c0 = t * 16 + 2 * p;
    float v0 = (o < SS && c0 < K) ? W[(size_t)c0 * SS + o] : 0.f;
    float v1 = (o < SS && c0 + 1 < K) ? W[(size_t)(c0 + 1) * SS + o] : 0.f;
    uint32_t hp, lp;
    split2(v0, v1, hp, lp);
    int nt = o >> 3, nr = o & 7, ks = p >> 2, j = p & 3;
    size_t off = (size_t)t * BBLK + (nt * 2 + ks) * 128 + nr * 16 + j * 4;
    *(uint32_t*)(img + off) = hp;
    *(uint32_t*)(img + off + BSPLIT) = lp;
}

// ---- main ----
__device__ __forceinline__ void prefetchB(const unsigned char* img, int t, int T,
                                          uint32_t sb, int tid)
{
    if (t < T) {
        const unsigned char* src = img + (size_t)t * BBLK;
        uint32_t dst = sb + SM_B + (uint32_t)(t & 3) * (uint32_t)BBLK;
        for (int i = tid; i < BBLK / 16; i += NT)
            cp_async16(dst + 16u * (uint32_t)i, src + 16 * i);
    }
    cp_commit();
}

// Build A (z products) as packed 8x8 mats, bf16 hi/lo. 512 threads, 2 words each.
template <int NF>
__device__ __forceinline__ void stageA(int t, int K, const float* xs, const float* h,
                                       char* abuf, int tid)
{
    int r = tid & 127;          // M row
    int kq = tid >> 7;          // 0..3 (k quad: 4 k-values)
    int bl = r >> 5, d = r & 31;
    const float* xb = xs + bl * F0C * DD + d;
    const float* hb = h + bl * NF * DD + d;
    int cb = t * 16 + kq * 4;
    uint32_t hp[2], lp[2];
#pragma unroll
    for (int j = 0; j < 2; j++) {
        int c0 = cb + 2 * j;
        float p0 = 0.f, p1 = 0.f;
        if (c0 < K)     p0 = xb[(c0 / NF) * DD] * hb[(c0 % NF) * DD];
        if (c0 + 1 < K) p1 = xb[((c0 + 1) / NF) * DD] * hb[((c0 + 1) % NF) * DD];
        split2(p0, p1, hp[j], lp[j]);
    }
    uint32_t off = (uint32_t)((((r >> 3) * 2 + (kq >> 1)) << 7) + (r & 7) * 16 + (kq & 1) * 8);
    *(uint2*)(abuf + off) = make_uint2(hp[0], hp[1]);
    *(uint2*)(abuf + ASPLIT + off) = make_uint2(lp[0], lp[1]);
}

template <int NF, int LMODE>
__device__ void run_layer(const unsigned char* img, int T, int K,
                          const float* xs, const float* hsrc, float* hs,
                          const float* bias, float* out,
                          char* smem, uint32_t sb, int bbase, int Btot)
{
    const int tid = threadIdx.x;
    const int w = tid >> 5, lane = tid & 31;
    const int mq = w >> 1, nh = w & 1;   // mq 0..7 (m16 tile), nh 0..1 (N half)

    float acc[13][4];
#pragma unroll
    for (int nt = 0; nt < 13; nt++)
#pragma unroll
        for (int q = 0; q < 4; q++) acc[nt][q] = 0.f;

    prefetchB(img, 0, T, sb, tid);
    prefetchB(img, 1, T, sb, tid);
    prefetchB(img, 2, T, sb, tid);
    stageA<NF>(0, K, xs, hsrc, smem + SM_A, tid);

    const uint32_t aoff = ((lane >> 3) & 1) * 256u + ((lane >> 3) >> 1) * 128u + (lane & 7) * 16u;
    const uint32_t boff = (uint32_t)lane * 16u;
    const uint32_t boff2 = (uint32_t)(lane & 15) * 16u;

    for (int t = 0; t < T; t++) {
        cp_wait<2>();
        __syncthreads();
        prefetchB(img, t + 3, T, sb, tid);

        uint32_t ab = sb + SM_A + (uint32_t)(t & 1) * ABUF + (uint32_t)mq * 512u;
        uint32_t ah[4], al[4];
        ldsm4(ah, ab + aoff);
        ldsm4(al, ab + ASPLIT + aoff);

        uint32_t bb = sb + SM_B + (uint32_t)(t & 3) * (uint32_t)BBLK + (uint32_t)nh * 3328u;
#pragma unroll
        for (int i = 0; i < 6; i++) {
            uint32_t bh[4], bl4[4];
            ldsm4(bh, bb + i * 512u + boff);
            ldsm4(bl4, bb + BSPLIT + i * 512u + boff);
            MMA(acc[2 * i], ah, bh[0], bh[1]);
            MMA(acc[2 * i], ah, bl4[0], bl4[1]);
            MMA(acc[2 * i], al, bh[0], bh[1]);
            MMA(acc[2 * i + 1], ah, bh[2], bh[3]);
            MMA(acc[2 * i + 1], ah, bl4[2], bl4[3]);
            MMA(acc[2 * i + 1], al, bh[2], bh[3]);
        }
        {
            uint32_t bh2[2], bl2[2];
            ldsm2(bh2, bb + 3072u + boff2);
            ldsm2(bl2, bb + BSPLIT + 3072u + boff2);
            MMA(acc[12], ah, bh2[0], bh2[1]);
            MMA(acc[12], ah, bl2[0], bl2[1]);
            MMA(acc[12], al, bh2[0], bh2[1]);
        }
        if (t + 1 < T)
            stageA<NF>(t + 1, K, xs, hsrc, smem + SM_A + ((t + 1) & 1) * ABUF, tid);
    }
    cp_wait<0>();
    __syncthreads();   // all MMA reads of A bufs done before pbuf reuses SM_A

    // ---- epilogue: bias+relu, hidden writeback, warp-partial d-sums ----
    float* pbuf = (float*)(smem + SM_A);    // [8][NPAD] partial sums
    int bl = mq >> 1;
    int quad = lane & 3, ldq = lane >> 2;
    int d0 = (mq & 1) * 16 + ldq;           // row mq*16+ldq -> d
    const float* bi = bias + LMODE * SS;
#pragma unroll
    for (int nt = 0; nt < 13; nt++) {
        int oe = nh * 104 + nt * 8 + 2 * quad;
        float be = bi[oe], bo = bi[oe + 1];
        float v0 = fmaxf(acc[nt][0] + be, 0.f);
        float v1 = fmaxf(acc[nt][1] + bo, 0.f);
        float v2 = fmaxf(acc[nt][2] + be, 0.f);
        float v3 = fmaxf(acc[nt][3] + bo, 0.f);
        if (LMODE < 2) {
            if (oe < NFH) {
                hs[(bl * NFH + oe) * DD + d0] = v0;
                hs[(bl * NFH + oe) * DD + d0 + 8] = v2;
            }
            if (oe + 1 < NFH) {
                hs[(bl * NFH + oe + 1) * DD + d0] = v1;
                hs[(bl * NFH + oe + 1) * DD + d0 + 8] = v3;
            }
        }
        float se = v0 + v2, so = v1 + v3;
        se += __shfl_xor_sync(0xffffffffu, se, 4);
        se += __shfl_xor_sync(0xffffffffu, se, 8);
        se += __shfl_xor_sync(0xffffffffu, se, 16);
        so += __shfl_xor_sync(0xffffffffu, so, 4);
        so += __shfl_xor_sync(0xffffffffu, so, 8);
        so += __shfl_xor_sync(0xffffffffu, so, 16);
        if (ldq == 0) {
            pbuf[mq * NPAD + oe] = se;
            pbuf[mq * NPAD + oe + 1] = so;
        }
    }
    __syncthreads();

    // combine mq pairs (d 0-15 + d 16-31) and store direct outputs
    for (int idx = tid; idx < 4 * NPAD; idx += NT) {
        int blc = idx / NPAD, o = idx - blc * NPAD;
        bool dir = (LMODE == 2) ? (o < SS) : (o >= NFH && o < SS);
        int b = bbase + blc;
        if (dir && b < Btot) {
            float v = pbuf[(2 * blc) * NPAD + o] + pbuf[(2 * blc + 1) * NPAD + o];
            int ch = (LMODE == 0) ? (o - NFH) : (LMODE == 1) ? o : (SS + o);
            out[(size_t)b * (2 * SS) + ch] = v;
        }
    }
    __syncthreads();
}

__global__ void __launch_bounds__(NT, 1)
cin_main(const float* __restrict__ x,
         const float* __restrict__ b0g, const float* __restrict__ b1g,
         const float* __restrict__ b2g,
         float* __restrict__ out, int Btot)
{
    extern __shared__ char smem[];
    uint32_t sb = (uint32_t)__cvta_generic_to_shared(smem);
    int tid = threadIdx.x;

    float* bias = (float*)(smem + SM_BIAS);
    for (int i = tid; i < 3 * SS; i += NT)
        bias[i] = (i < SS) ? b0g[i] : (i < 2 * SS) ? b1g[i - SS] : b2g[i - 2 * SS];

    float* xs = (float*)(smem + SM_X);
    float* hs = (float*)(smem + SM_H);
    int bbase = blockIdx.x * 4;
    for (int bl = 0; bl < 4; bl++) {
        int b = bbase + bl;
        float4* dst = (float4*)(xs + bl * F0C * DD);
        if (b < Btot) {
            const float4* src = (const float4*)(x + (size_t)b * (F0C * DD));
            for (int i = tid; i < F0C * DD / 4; i += NT) dst[i] = src[i];
        } else {
            float4 z = make_float4(0.f, 0.f, 0.f, 0.f);
            for (int i = tid; i < F0C * DD / 4; i += NT) dst[i] = z;
        }
    }
    __syncthreads();

    run_layer<F0C, 0>(g_wimg, T0, K0, xs, xs, hs, bias, out, smem, sb, bbase, Btot);
    run_layer<NFH, 1>(g_wimg + IMG0_BYTES, T12, K12, xs, hs, hs, bias, out, smem, sb, bbase, Btot);
    run_layer<NFH, 2>(g_wimg + IMG0_BYTES + IMG12_BYTES, T12, K12, xs, hs, hs, bias, out, smem, sb, bbase, Btot);
}

extern "C" void kernel_launch(void* const* d_in, const int* in_sizes, int n_in,
                              void* d_out, int out_size)
{
    const float* x = nullptr;
    const float* W0 = nullptr;
    const float* W1 = nullptr;
    const float* W2 = nullptr;
    const float* bb[3] = {nullptr, nullptr, nullptr};
    int nb = 0;
    long xsz = 0;

    for (int i = 0; i < n_in; i++) {
        long sz = in_sizes[i];
        const float* p = (const float*)d_in[i];
        if (sz == (long)K0 * SS) W0 = p;
        else if (sz == (long)K12 * SS) { if (!W1) W1 = p; else W2 = p; }
        else if (sz == SS) { if (nb < 3) bb[nb++] = p; }
        else { x = p; xsz = sz; }
    }

    int B = (int)(xsz / (F0C * DD));

    int n0 = T0 * 8 * NPAD, n12 = T12 * 8 * NPAD;
    prep_kernel<<<(n0 + 255) / 256, 256>>>(W0, K0, T0, 0);
    prep_kernel<<<(n12 + 255) / 256, 256>>>(W1, K12, T12, 1);
    prep_kernel<<<(n12 + 255) / 256, 256>>>(W2, K12, T12, 2);

    cudaFuncSetAttribute(cin_main, cudaFuncAttributeMaxDynamicSharedMemorySize, SMEM_TOTAL);
    cin_main<<<(B + 3) / 4, NT, SMEM_TOTAL>>>(x, bb[0], bb[1], bb[2], (float*)d_out, B);
}

// round 6
// speedup vs baseline: 5.3293x; 1.7734x over previous
#include <cuda_runtime.h>
#include <cstdint>

#define F0C 39
#define DD 32
#define SS 200
#define NFH 100
#define NPAD 208
#define K0 1521
#define T0 96
#define K12 3900
#define T12 244

#define ABUF   4096                 // one A buffer: 128x16 fp16
#define BBLK   6656                 // one B k-step image: 16x208 fp16
#define IMG0_BYTES (T0 * BBLK)
#define IMG12_BYTES (T12 * BBLK)

#define SM_BIAS 0
#define SM_X    2432
#define SM_H    22400
#define SM_A    73600               // 2 * 4096
#define SM_B    81792               // 4 * 6656
#define SMEM_TOTAL 108416

#define NT 512

__device__ __align__(16) unsigned char g_wimg[IMG0_BYTES + 2 * IMG12_BYTES];

__device__ __forceinline__ void cp_async16(uint32_t s, const void* g) {
    asm volatile("cp.async.cg.shared.global [%0], [%1], 16;\n" :: "r"(s), "l"(g) : "memory");
}
__device__ __forceinline__ void cp_commit() { asm volatile("cp.async.commit_group;\n" ::: "memory"); }
template <int N> __device__ __forceinline__ void cp_wait() {
    asm volatile("cp.async.wait_group %0;\n" :: "n"(N) : "memory");
}
// pack two f32 -> f16x2 (p0 in low half = first k)
__device__ __forceinline__ uint32_t cvth2(float p0, float p1) {
    uint32_t r;
    asm("cvt.rn.f16x2.f32 %0, %1, %2;" : "=r"(r) : "f"(p1), "f"(p0));
    return r;
}
__device__ __forceinline__ void ldsm4(uint32_t* r, uint32_t a) {
    asm volatile("ldmatrix.sync.aligned.m8n8.x4.shared.b16 {%0,%1,%2,%3}, [%4];"
                 : "=r"(r[0]), "=r"(r[1]), "=r"(r[2]), "=r"(r[3]) : "r"(a));
}
__device__ __forceinline__ void ldsm2(uint32_t* r, uint32_t a) {
    asm volatile("ldmatrix.sync.aligned.m8n8.x2.shared.b16 {%0,%1}, [%2];"
                 : "=r"(r[0]), "=r"(r[1]) : "r"(a));
}
#define MMA(D, A, B0, B1)                                                     \
    asm volatile("mma.sync.aligned.m16n8k16.row.col.f32.f16.f16.f32 "         \
                 "{%0,%1,%2,%3}, {%4,%5,%6,%7}, {%8,%9}, {%0,%1,%2,%3};"      \
                 : "+f"(D[0]), "+f"(D[1]), "+f"(D[2]), "+f"(D[3])             \
                 : "r"((A)[0]), "r"((A)[1]), "r"((A)[2]), "r"((A)[3]),        \
                   "r"(B0), "r"(B1))

// ---- prep: W[K,200] -> tile-packed fp16 images (8x8 mats, n-major rows) ----
__global__ void prep_kernel(const float* __restrict__ W, int K, int T, int which)
{
    unsigned char* img = g_wimg +
        ((which == 0) ? 0 : (which == 1) ? IMG0_BYTES : (IMG0_BYTES + IMG12_BYTES));
    int idx = blockIdx.x * 256 + threadIdx.x;
    if (idx >= T * 8 * NPAD) return;
    int o = idx % NPAD;
    int r = idx / NPAD;
    int p = r & 7, t = r >> 3;
    int c0 = t * 16 + 2 * p;
    float v0 = (o < SS && c0 < K) ? W[(size_t)c0 * SS + o] : 0.f;
    float v1 = (o < SS && c0 + 1 < K) ? W[(size_t)(c0 + 1) * SS + o] : 0.f;
    uint32_t hp = cvth2(v0, v1);
    int nt = o >> 3, nr = o & 7, ks = p >> 2, j = p & 3;
    size_t off = (size_t)t * BBLK + (nt * 2 + ks) * 128 + nr * 16 + j * 4;
    *(uint32_t*)(img + off) = hp;
}

// ---- main ----
__device__ __forceinline__ void prefetchB(const unsigned char* img, int t, int T,
                                          uint32_t sb, int tid)
{
    if (t < T) {
        const unsigned char* src = img + (size_t)t * BBLK;
        uint32_t dst = sb + SM_B + (uint32_t)(t & 3) * (uint32_t)BBLK;
        for (int i = tid; i < BBLK / 16; i += NT)
            cp_async16(dst + 16u * (uint32_t)i, src + 16 * i);
    }
    cp_commit();
}

// Build A (z products) as packed 8x8 fp16 mats. 512 threads, 1 uint2 each.
template <int NF>
__device__ __forceinline__ void stageA(int t, int K, const float* xs, const float* h,
                                       char* abuf, int tid)
{
    int r = tid & 127;          // M row
    int kq = tid >> 7;          // 0..3 (4 k-values each)
    int bl = r >> 5, d = r & 31;
    const float* xb = xs + bl * F0C * DD + d;
    const float* hb = h + bl * NF * DD + d;
    int cb = t * 16 + kq * 4;
    uint32_t hp[2];
#pragma unroll
    for (int j = 0; j < 2; j++) {
        int c0 = cb + 2 * j;
        float p0 = 0.f, p1 = 0.f;
        if (c0 < K)     p0 = xb[(c0 / NF) * DD] * hb[(c0 % NF) * DD];
        if (c0 + 1 < K) p1 = xb[((c0 + 1) / NF) * DD] * hb[((c0 + 1) % NF) * DD];
        hp[j] = cvth2(p0, p1);
    }
    uint32_t off = (uint32_t)((((r >> 3) * 2 + (kq >> 1)) << 7) + (r & 7) * 16 + (kq & 1) * 8);
    *(uint2*)(abuf + off) = make_uint2(hp[0], hp[1]);
}

template <int NF, int LMODE>
__device__ void run_layer(const unsigned char* img, int T, int K,
                          const float* xs, const float* hsrc, float* hs,
                          const float* bias, float* out,
                          char* smem, uint32_t sb, int bbase, int Btot)
{
    const int tid = threadIdx.x;
    const int w = tid >> 5, lane = tid & 31;
    const int mq = w >> 1, nh = w & 1;   // mq 0..7 (m16 tile), nh 0..1 (N half)

    float acc[13][4];
#pragma unroll
    for (int nt = 0; nt < 13; nt++)
#pragma unroll
        for (int q = 0; q < 4; q++) acc[nt][q] = 0.f;

    prefetchB(img, 0, T, sb, tid);
    prefetchB(img, 1, T, sb, tid);
    prefetchB(img, 2, T, sb, tid);
    stageA<NF>(0, K, xs, hsrc, smem + SM_A, tid);

    const uint32_t aoff = ((lane >> 3) & 1) * 256u + ((lane >> 3) >> 1) * 128u + (lane & 7) * 16u;
    const uint32_t boff = (uint32_t)lane * 16u;
    const uint32_t boff2 = (uint32_t)(lane & 15) * 16u;

    for (int t = 0; t < T; t++) {
        cp_wait<2>();
        __syncthreads();
        prefetchB(img, t + 3, T, sb, tid);

        uint32_t ab = sb + SM_A + (uint32_t)(t & 1) * ABUF + (uint32_t)mq * 512u;
        uint32_t ah[4];
        ldsm4(ah, ab + aoff);

        uint32_t bb = sb + SM_B + (uint32_t)(t & 3) * (uint32_t)BBLK + (uint32_t)nh * 3328u;
#pragma unroll
        for (int i = 0; i < 6; i++) {
            uint32_t bh[4];
            ldsm4(bh, bb + i * 512u + boff);
            MMA(acc[2 * i], ah, bh[0], bh[1]);
            MMA(acc[2 * i + 1], ah, bh[2], bh[3]);
        }
        {
            uint32_t bh2[2];
            ldsm2(bh2, bb + 3072u + boff2);
            MMA(acc[12], ah, bh2[0], bh2[1]);
        }
        if (t + 1 < T)
            stageA<NF>(t + 1, K, xs, hsrc, smem + SM_A + ((t + 1) & 1) * ABUF, tid);
    }
    cp_wait<0>();
    __syncthreads();   // all MMA reads of A bufs done before pbuf reuses SM_A

    // ---- epilogue: bias+relu, hidden writeback, warp-partial d-sums ----
    float* pbuf = (float*)(smem + SM_A);    // [8][NPAD] partial sums
    int bl = mq >> 1;
    int quad = lane & 3, ldq = lane >> 2;
    int d0 = (mq & 1) * 16 + ldq;           // row mq*16+ldq -> d
    const float* bi = bias + LMODE * SS;
#pragma unroll
    for (int nt = 0; nt < 13; nt++) {
        int oe = nh * 104 + nt * 8 + 2 * quad;
        float be = bi[oe], bo = bi[oe + 1];
        float v0 = fmaxf(acc[nt][0] + be, 0.f);
        float v1 = fmaxf(acc[nt][1] + bo, 0.f);
        float v2 = fmaxf(acc[nt][2] + be, 0.f);
        float v3 = fmaxf(acc[nt][3] + bo, 0.f);
        if (LMODE < 2) {
            if (oe < NFH) {
                hs[(bl * NFH + oe) * DD + d0] = v0;
                hs[(bl * NFH + oe) * DD + d0 + 8] = v2;
            }
            if (oe + 1 < NFH) {
                hs[(bl * NFH + oe + 1) * DD + d0] = v1;
                hs[(bl * NFH + oe + 1) * DD + d0 + 8] = v3;
            }
        }
        float se = v0 + v2, so = v1 + v3;
        se += __shfl_xor_sync(0xffffffffu, se, 4);
        se += __shfl_xor_sync(0xffffffffu, se, 8);
        se += __shfl_xor_sync(0xffffffffu, se, 16);
        so += __shfl_xor_sync(0xffffffffu, so, 4);
        so += __shfl_xor_sync(0xffffffffu, so, 8);
        so += __shfl_xor_sync(0xffffffffu, so, 16);
        if (ldq == 0) {
            pbuf[mq * NPAD + oe] = se;
            pbuf[mq * NPAD + oe + 1] = so;
        }
    }
    __syncthreads();

    // combine mq pairs (d 0-15 + d 16-31) and store direct outputs
    for (int idx = tid; idx < 4 * NPAD; idx += NT) {
        int blc = idx / NPAD, o = idx - blc * NPAD;
        bool dir = (LMODE == 2) ? (o < SS) : (o >= NFH && o < SS);
        int b = bbase + blc;
        if (dir && b < Btot) {
            float v = pbuf[(2 * blc) * NPAD + o] + pbuf[(2 * blc + 1) * NPAD + o];
            int ch = (LMODE == 0) ? (o - NFH) : (LMODE == 1) ? o : (SS + o);
            out[(size_t)b * (2 * SS) + ch] = v;
        }
    }
    __syncthreads();
}

__global__ void __launch_bounds__(NT, 1)
cin_main(const float* __restrict__ x,
         const float* __restrict__ b0g, const float* __restrict__ b1g,
         const float* __restrict__ b2g,
         float* __restrict__ out, int Btot)
{
    extern __shared__ char smem[];
    uint32_t sb = (uint32_t)__cvta_generic_to_shared(smem);
    int tid = threadIdx.x;

    float* bias = (float*)(smem + SM_BIAS);
    for (int i = tid; i < 3 * SS; i += NT)
        bias[i] = (i < SS) ? b0g[i] : (i < 2 * SS) ? b1g[i - SS] : b2g[i - 2 * SS];

    float* xs = (float*)(smem + SM_X);
    float* hs = (float*)(smem + SM_H);
    int bbase = blockIdx.x * 4;
    for (int bl = 0; bl < 4; bl++) {
        int b = bbase + bl;
        float4* dst = (float4*)(xs + bl * F0C * DD);
        if (b < Btot) {
            const float4* src = (const float4*)(x + (size_t)b * (F0C * DD));
            for (int i = tid; i < F0C * DD / 4; i += NT) dst[i] = src[i];
        } else {
            float4 z = make_float4(0.f, 0.f, 0.f, 0.f);
            for (int i = tid; i < F0C * DD / 4; i += NT) dst[i] = z;
        }
    }
    __syncthreads();

    run_layer<F0C, 0>(g_wimg, T0, K0, xs, xs, hs, bias, out, smem, sb, bbase, Btot);
    run_layer<NFH, 1>(g_wimg + IMG0_BYTES, T12, K12, xs, hs, hs, bias, out, smem, sb, bbase, Btot);
    run_layer<NFH, 2>(g_wimg + IMG0_BYTES + IMG12_BYTES, T12, K12, xs, hs, hs, bias, out, smem, sb, bbase, Btot);
}

extern "C" void kernel_launch(void* const* d_in, const int* in_sizes, int n_in,
                              void* d_out, int out_size)
{
    const float* x = nullptr;
    const float* W0 = nullptr;
    const float* W1 = nullptr;
    const float* W2 = nullptr;
    const float* bb[3] = {nullptr, nullptr, nullptr};
    int nb = 0;
    long xsz = 0;

    for (int i = 0; i < n_in; i++) {
        long sz = in_sizes[i];
        const float* p = (const float*)d_in[i];
        if (sz == (long)K0 * SS) W0 = p;
        else if (sz == (long)K12 * SS) { if (!W1) W1 = p; else W2 = p; }
        else if (sz == SS) { if (nb < 3) bb[nb++] = p; }
        else { x = p; xsz = sz; }
    }

    int B = (int)(xsz / (F0C * DD));

    int n0 = T0 * 8 * NPAD, n12 = T12 * 8 * NPAD;
    prep_kernel<<<(n0 + 255) / 256, 256>>>(W0, K0, T0, 0);
    prep_kernel<<<(n12 + 255) / 256, 256>>>(W1, K12, T12, 1);
    prep_kernel<<<(n12 + 255) / 256, 256>>>(W2, K12, T12, 2);

    cudaFuncSetAttribute(cin_main, cudaFuncAttributeMaxDynamicSharedMemorySize, SMEM_TOTAL);
    cin_main<<<(B + 3) / 4, NT, SMEM_TOTAL>>>(x, bb[0], bb[1], bb[2], (float*)d_out, B);
}

// round 7
// speedup vs baseline: 7.6983x; 1.4445x over previous
#include <cuda_runtime.h>
#include <cstdint>

#define F0C 39
#define DD 32
#define SS 200
#define NFH 100
#define NPAD 208
#define K0 1521
#define T0 96          // k16 tiles
#define K12 3900
#define T12 244

#define BBLK16 6656             // one k16 B image
#define BBLK32 13312            // one k32 block (2 contiguous k16 images)
#define ABUF32 8192             // one A buffer: 2 subtiles x 4096
#define IMG0_BYTES (T0 * BBLK16)
#define IMG12_BYTES (T12 * BBLK16)

#define SM_BIAS 0
#define SM_X    2432
#define SM_H    22400
#define SM_LUT  73600           // up to 3904 uint32 = 15616
#define SM_A    89216           // 2 * 8192
#define SM_B    105600          // 4 * 13312
#define SMEM_TOTAL 158848

#define NT 512

__device__ __align__(16) unsigned char g_wimg[IMG0_BYTES + 2 * IMG12_BYTES];

__device__ __forceinline__ void cp_async16(uint32_t s, const void* g) {
    asm volatile("cp.async.cg.shared.global [%0], [%1], 16;\n" :: "r"(s), "l"(g) : "memory");
}
__device__ __forceinline__ void cp_commit() { asm volatile("cp.async.commit_group;\n" ::: "memory"); }
template <int N> __device__ __forceinline__ void cp_wait() {
    asm volatile("cp.async.wait_group %0;\n" :: "n"(N) : "memory");
}
__device__ __forceinline__ uint32_t cvth2(float p0, float p1) {
    uint32_t r;
    asm("cvt.rn.f16x2.f32 %0, %1, %2;" : "=r"(r) : "f"(p1), "f"(p0));
    return r;
}
__device__ __forceinline__ void ldsm4(uint32_t* r, uint32_t a) {
    asm volatile("ldmatrix.sync.aligned.m8n8.x4.shared.b16 {%0,%1,%2,%3}, [%4];"
                 : "=r"(r[0]), "=r"(r[1]), "=r"(r[2]), "=r"(r[3]) : "r"(a));
}
__device__ __forceinline__ void ldsm2(uint32_t* r, uint32_t a) {
    asm volatile("ldmatrix.sync.aligned.m8n8.x2.shared.b16 {%0,%1}, [%2];"
                 : "=r"(r[0]), "=r"(r[1]) : "r"(a));
}
#define MMA(D, A, B0, B1)                                                     \
    asm volatile("mma.sync.aligned.m16n8k16.row.col.f32.f16.f16.f32 "         \
                 "{%0,%1,%2,%3}, {%4,%5,%6,%7}, {%8,%9}, {%0,%1,%2,%3};"      \
                 : "+f"(D[0]), "+f"(D[1]), "+f"(D[2]), "+f"(D[3])             \
                 : "r"((A)[0]), "r"((A)[1]), "r"((A)[2]), "r"((A)[3]),        \
                   "r"(B0), "r"(B1))

// ---- prep: W[K,200] -> tile-packed fp16 images (8x8 mats, n-major rows) ----
__global__ void prep_kernel(const float* __restrict__ W, int K, int T, int which)
{
    unsigned char* img = g_wimg +
        ((which == 0) ? 0 : (which == 1) ? IMG0_BYTES : (IMG0_BYTES + IMG12_BYTES));
    int idx = blockIdx.x * 256 + threadIdx.x;
    if (idx >= T * 8 * NPAD) return;
    int o = idx % NPAD;
    int r = idx / NPAD;
    int p = r & 7, t = r >> 3;
    int c0 = t * 16 + 2 * p;
    float v0 = (o < SS && c0 < K) ? W[(size_t)c0 * SS + o] : 0.f;
    float v1 = (o < SS && c0 + 1 < K) ? W[(size_t)(c0 + 1) * SS + o] : 0.f;
    uint32_t hp = cvth2(v0, v1);
    int nt = o >> 3, nr = o & 7, ks = p >> 2, j = p & 3;
    size_t off = (size_t)t * BBLK16 + (nt * 2 + ks) * 128 + nr * 16 + j * 4;
    *(uint32_t*)(img + off) = hp;
}

// ---- main ----
__device__ __forceinline__ void prefetchB(const unsigned char* img, int t, int T2,
                                          uint32_t sb, int tid)
{
    if (t < T2) {
        const unsigned char* src = img + (size_t)t * BBLK32;
        uint32_t dst = sb + SM_B + (uint32_t)(t & 3) * (uint32_t)BBLK32;
        for (int i = tid; i < BBLK32 / 16; i += NT)
            cp_async16(dst + 16u * (uint32_t)i, src + 16 * i);
    }
    cp_commit();
}

// Build A (z products) for one k32 block. 512 threads, 8 products + 1 STS.128 each.
template <int NF>
__device__ __forceinline__ void stageA(int t, const uint32_t* lut,
                                       const float* xs, const float* h,
                                       char* abuf, int tid)
{
    int r = tid & 127;          // M row
    int kq = tid >> 7;          // 0..3 -> 8 consecutive k each
    int bl = r >> 5, d = r & 31;
    const float* xb = xs + bl * F0C * DD + d;
    const float* hb = h + bl * NF * DD + d;
    int c0 = t * 32 + kq * 8;
    uint4 l0 = *(const uint4*)(lut + c0);
    uint4 l1 = *(const uint4*)(lut + c0 + 4);
    uint32_t hp[4];
    hp[0] = cvth2(xb[l0.x >> 16] * hb[l0.x & 0xffffu], xb[l0.y >> 16] * hb[l0.y & 0xffffu]);
    hp[1] = cvth2(xb[l0.z >> 16] * hb[l0.z & 0xffffu], xb[l0.w >> 16] * hb[l0.w & 0xffffu]);
    hp[2] = cvth2(xb[l1.x >> 16] * hb[l1.x & 0xffffu], xb[l1.y >> 16] * hb[l1.y & 0xffffu]);
    hp[3] = cvth2(xb[l1.z >> 16] * hb[l1.z & 0xffffu], xb[l1.w >> 16] * hb[l1.w & 0xffffu]);
    // subtile (kq>>1) 4096B, row-half (kq&1)
    uint32_t off = (uint32_t)(((kq >> 1) << 12) + (((r >> 3) * 2 + (kq & 1)) << 7) + (r & 7) * 16);
    *(uint4*)(abuf + off) = *(uint4*)hp;
}

template <int NF, int LMODE>
__device__ void run_layer(const unsigned char* img, int T2, int K,
                          const float* xs, const float* hsrc, float* hs,
                          const float* bias, float* out,
                          char* smem, uint32_t sb, int bbase, int Btot)
{
    const int tid = threadIdx.x;
    const int w = tid >> 5, lane = tid & 31;
    const int mq = w >> 1, nh = w & 1;

    // build index LUT (zero-offset padding: W image is 0 there, so products cancel)
    uint32_t* lut = (uint32_t*)(smem + SM_LUT);
    for (int c = tid; c < T2 * 32; c += NT) {
        int m = 0, n = 0;
        if (c < K) { m = c / NF; n = c - m * NF; }
        lut[c] = ((uint32_t)(m * DD) << 16) | (uint32_t)(n * DD);
    }

    float acc[13][4];
#pragma unroll
    for (int nt = 0; nt < 13; nt++)
#pragma unroll
        for (int q = 0; q < 4; q++) acc[nt][q] = 0.f;

    prefetchB(img, 0, T2, sb, tid);
    prefetchB(img, 1, T2, sb, tid);
    prefetchB(img, 2, T2, sb, tid);
    __syncthreads();                    // lut (and hsrc) visible
    stageA<NF>(0, lut, xs, hsrc, smem + SM_A, tid);

    const uint32_t aoff = ((lane >> 3) & 1) * 256u + ((lane >> 3) >> 1) * 128u + (lane & 7) * 16u;
    const uint32_t boff = (uint32_t)lane * 16u;
    const uint32_t boff2 = (uint32_t)(lane & 15) * 16u;

    for (int t = 0; t < T2; t++) {
        cp_wait<2>();
        __syncthreads();
        prefetchB(img, t + 3, T2, sb, tid);

        uint32_t ab = sb + SM_A + (uint32_t)(t & 1) * ABUF32 + (uint32_t)mq * 512u;
        uint32_t bbase2 = sb + SM_B + (uint32_t)(t & 3) * (uint32_t)BBLK32 + (uint32_t)nh * 3328u;
#pragma unroll
        for (int s = 0; s < 2; s++) {
            uint32_t ah[4];
            ldsm4(ah, ab + (uint32_t)s * 4096u + aoff);
            uint32_t bb = bbase2 + (uint32_t)s * (uint32_t)BBLK16;
#pragma unroll
            for (int i = 0; i < 6; i++) {
                uint32_t bh[4];
                ldsm4(bh, bb + i * 512u + boff);
                MMA(acc[2 * i], ah, bh[0], bh[1]);
                MMA(acc[2 * i + 1], ah, bh[2], bh[3]);
            }
            uint32_t bh2[2];
            ldsm2(bh2, bb + 3072u + boff2);
            MMA(acc[12], ah, bh2[0], bh2[1]);
        }
        if (t + 1 < T2)
            stageA<NF>(t + 1, lut, xs, hsrc, smem + SM_A + ((t + 1) & 1) * ABUF32, tid);
    }
    cp_wait<0>();
    __syncthreads();   // all MMA reads of A bufs done before pbuf reuses SM_A

    // ---- epilogue: bias+relu, hidden writeback, warp-partial d-sums ----
    float* pbuf = (float*)(smem + SM_A);    // [8][NPAD]
    int bl = mq >> 1;
    int quad = lane & 3, ldq = lane >> 2;
    int d0 = (mq & 1) * 16 + ldq;
    const float* bi = bias + LMODE * SS;
#pragma unroll
    for (int nt = 0; nt < 13; nt++) {
        int oe = nh * 104 + nt * 8 + 2 * quad;
        float be = bi[oe], bo = bi[oe + 1];
        float v0 = fmaxf(acc[nt][0] + be, 0.f);
        float v1 = fmaxf(acc[nt][1] + bo, 0.f);
        float v2 = fmaxf(acc[nt][2] + be, 0.f);
        float v3 = fmaxf(acc[nt][3] + bo, 0.f);
        if (LMODE < 2) {
            if (oe < NFH) {
                hs[(bl * NFH + oe) * DD + d0] = v0;
                hs[(bl * NFH + oe) * DD + d0 + 8] = v2;
            }
            if (oe + 1 < NFH) {
                hs[(bl * NFH + oe + 1) * DD + d0] = v1;
                hs[(bl * NFH + oe + 1) * DD + d0 + 8] = v3;
            }
        }
        float se = v0 + v2, so = v1 + v3;
        se += __shfl_xor_sync(0xffffffffu, se, 4);
        se += __shfl_xor_sync(0xffffffffu, se, 8);
        se += __shfl_xor_sync(0xffffffffu, se, 16);
        so += __shfl_xor_sync(0xffffffffu, so, 4);
        so += __shfl_xor_sync(0xffffffffu, so, 8);
        so += __shfl_xor_sync(0xffffffffu, so, 16);
        if (ldq == 0) {
            pbuf[mq * NPAD + oe] = se;
            pbuf[mq * NPAD + oe + 1] = so;
        }
    }
    __syncthreads();

    for (int idx = tid; idx < 4 * NPAD; idx += NT) {
        int blc = idx / NPAD, o = idx - blc * NPAD;
        bool dir = (LMODE == 2) ? (o < SS) : (o >= NFH && o < SS);
        int b = bbase + blc;
        if (dir && b < Btot) {
            float v = pbuf[(2 * blc) * NPAD + o] + pbuf[(2 * blc + 1) * NPAD + o];
            int ch = (LMODE == 0) ? (o - NFH) : (LMODE == 1) ? o : (SS + o);
            out[(size_t)b * (2 * SS) + ch] = v;
        }
    }
    __syncthreads();
}

__global__ void __launch_bounds__(NT, 1)
cin_main(const float* __restrict__ x,
         const float* __restrict__ b0g, const float* __restrict__ b1g,
         const float* __restrict__ b2g,
         float* __restrict__ out, int Btot)
{
    extern __shared__ char smem[];
    uint32_t sb = (uint32_t)__cvta_generic_to_shared(smem);
    int tid = threadIdx.x;

    float* bias = (float*)(smem + SM_BIAS);
    for (int i = tid; i < 3 * SS; i += NT)
        bias[i] = (i < SS) ? b0g[i] : (i < 2 * SS) ? b1g[i - SS] : b2g[i - 2 * SS];

    float* xs = (float*)(smem + SM_X);
    float* hs = (float*)(smem + SM_H);
    int bbase = blockIdx.x * 4;
    for (int bl = 0; bl < 4; bl++) {
        int b = bbase + bl;
        float4* dst = (float4*)(xs + bl * F0C * DD);
        if (b < Btot) {
            const float4* src = (const float4*)(x + (size_t)b * (F0C * DD));
            for (int i = tid; i < F0C * DD / 4; i += NT) dst[i] = src[i];
        } else {
            float4 z = make_float4(0.f, 0.f, 0.f, 0.f);
            for (int i = tid; i < F0C * DD / 4; i += NT) dst[i] = z;
        }
    }
    __syncthreads();

    run_layer<F0C, 0>(g_wimg, T0 / 2, K0, xs, xs, hs, bias, out, smem, sb, bbase, Btot);
    run_layer<NFH, 1>(g_wimg + IMG0_BYTES, T12 / 2, K12, xs, hs, hs, bias, out, smem, sb, bbase, Btot);
    run_layer<NFH, 2>(g_wimg + IMG0_BYTES + IMG12_BYTES, T12 / 2, K12, xs, hs, hs, bias, out, smem, sb, bbase, Btot);
}

extern "C" void kernel_launch(void* const* d_in, const int* in_sizes, int n_in,
                              void* d_out, int out_size)
{
    const float* x = nullptr;
    const float* W0 = nullptr;
    const float* W1 = nullptr;
    const float* W2 = nullptr;
    const float* bb[3] = {nullptr, nullptr, nullptr};
    int nb = 0;
    long xsz = 0;

    for (int i = 0; i < n_in; i++) {
        long sz = in_sizes[i];
        const float* p = (const float*)d_in[i];
        if (sz == (long)K0 * SS) W0 = p;
        else if (sz == (long)K12 * SS) { if (!W1) W1 = p; else W2 = p; }
        else if (sz == SS) { if (nb < 3) bb[nb++] = p; }
        else { x = p; xsz = sz; }
    }

    int B = (int)(xsz / (F0C * DD));

    int n0 = T0 * 8 * NPAD, n12 = T12 * 8 * NPAD;
    prep_kernel<<<(n0 + 255) / 256, 256>>>(W0, K0, T0, 0);
    prep_kernel<<<(n12 + 255) / 256, 256>>>(W1, K12, T12, 1);
    prep_kernel<<<(n12 + 255) / 256, 256>>>(W2, K12, T12, 2);

    cudaFuncSetAttribute(cin_main, cudaFuncAttributeMaxDynamicSharedMemorySize, SMEM_TOTAL);
    cin_main<<<(B + 3) / 4, NT, SMEM_TOTAL>>>(x, bb[0], bb[1], bb[2], (float*)d_out, B);
}

// round 8
// speedup vs baseline: 8.4322x; 1.0953x over previous
#include <cuda_runtime.h>
#include <cstdint>

#define F0C 39
#define DD 32
#define SS 200
#define NFH 100
#define NPAD 208
#define K0 1521
#define T0 96          // k16 tiles
#define K12 3900
#define T12 244

#define NBATCH 6                // batches per CTA
#define MROWS 192               // NBATCH * 32
#define NT 384                  // 12 warps

#define BBLK16 6656             // one k16 B image
#define BBLK32 13312
#define ABUF32 12288            // one A buffer: 2 subtiles x 6144 (192 rows x k16)
#define IMG0_BYTES (T0 * BBLK16)
#define IMG12_BYTES (T12 * BBLK16)

#define SM_BIAS 0               // 600 f -> 2400, pad 2432
#define SM_X    2432            // 6*39*32*4 = 29952 -> 32384
#define SM_H    32384           // 6*100*32*4 = 76800 -> 109184
#define SM_LUT  109184          // 3904*4 = 15616 -> 124800
#define SM_A    124800          // 2 * 12288 -> 149376
#define SM_B    149376          // 4 * 13312 -> 202624
#define SMEM_TOTAL 202624

__device__ __align__(16) unsigned char g_wimg[IMG0_BYTES + 2 * IMG12_BYTES];

__device__ __forceinline__ void cp_async16(uint32_t s, const void* g) {
    asm volatile("cp.async.cg.shared.global [%0], [%1], 16;\n" :: "r"(s), "l"(g) : "memory");
}
__device__ __forceinline__ void cp_commit() { asm volatile("cp.async.commit_group;\n" ::: "memory"); }
template <int N> __device__ __forceinline__ void cp_wait() {
    asm volatile("cp.async.wait_group %0;\n" :: "n"(N) : "memory");
}
__device__ __forceinline__ uint32_t cvth2(float p0, float p1) {
    uint32_t r;
    asm("cvt.rn.f16x2.f32 %0, %1, %2;" : "=r"(r) : "f"(p1), "f"(p0));
    return r;
}
__device__ __forceinline__ void ldsm4(uint32_t* r, uint32_t a) {
    asm volatile("ldmatrix.sync.aligned.m8n8.x4.shared.b16 {%0,%1,%2,%3}, [%4];"
                 : "=r"(r[0]), "=r"(r[1]), "=r"(r[2]), "=r"(r[3]) : "r"(a));
}
__device__ __forceinline__ void ldsm2(uint32_t* r, uint32_t a) {
    asm volatile("ldmatrix.sync.aligned.m8n8.x2.shared.b16 {%0,%1}, [%2];"
                 : "=r"(r[0]), "=r"(r[1]) : "r"(a));
}
#define MMA(D, A, B0, B1)                                                     \
    asm volatile("mma.sync.aligned.m16n8k16.row.col.f32.f16.f16.f32 "         \
                 "{%0,%1,%2,%3}, {%4,%5,%6,%7}, {%8,%9}, {%0,%1,%2,%3};"      \
                 : "+f"(D[0]), "+f"(D[1]), "+f"(D[2]), "+f"(D[3])             \
                 : "r"((A)[0]), "r"((A)[1]), "r"((A)[2]), "r"((A)[3]),        \
                   "r"(B0), "r"(B1))

// ---- prep: W[K,200] -> tile-packed fp16 images (8x8 mats, n-major rows) ----
__global__ void prep_kernel(const float* __restrict__ W, int K, int T, int which)
{
    unsigned char* img = g_wimg +
        ((which == 0) ? 0 : (which == 1) ? IMG0_BYTES : (IMG0_BYTES + IMG12_BYTES));
    int idx = blockIdx.x * 256 + threadIdx.x;
    if (idx >= T * 8 * NPAD) return;
    int o = idx % NPAD;
    int r = idx / NPAD;
    int p = r & 7, t = r >> 3;
    int c0 = t * 16 + 2 * p;
    float v0 = (o < SS && c0 < K) ? W[(size_t)c0 * SS + o] : 0.f;
    float v1 = (o < SS && c0 + 1 < K) ? W[(size_t)(c0 + 1) * SS + o] : 0.f;
    uint32_t hp = cvth2(v0, v1);
    int nt = o >> 3, nr = o & 7, ks = p >> 2, j = p & 3;
    size_t off = (size_t)t * BBLK16 + (nt * 2 + ks) * 128 + nr * 16 + j * 4;
    *(uint32_t*)(img + off) = hp;
}

// ---- main ----
__device__ __forceinline__ void prefetchB(const unsigned char* img, int t, int T2,
                                          uint32_t sb, int tid)
{
    if (t < T2) {
        const unsigned char* src = img + (size_t)t * BBLK32;
        uint32_t dst = sb + SM_B + (uint32_t)(t & 3) * (uint32_t)BBLK32;
        for (int i = tid; i < BBLK32 / 16; i += NT)
            cp_async16(dst + 16u * (uint32_t)i, src + 16 * i);
    }
    cp_commit();
}

// Build A (z products) for one k32 block: 192 rows x 32 k.
// Thread (r = tid%192, s = tid/192) handles all 16 k of subtile s for row r.
template <int NF>
__device__ __forceinline__ void stageA(int t, const uint32_t* lut,
                                       const float* xb, const float* hb,
                                       char* abuf, int r, int s)
{
    int cb = t * 32 + s * 16;
    uint32_t base = (uint32_t)(s * 6144 + ((r >> 3) * 2) * 128 + (r & 7) * 16);
#pragma unroll
    for (int kh = 0; kh < 2; kh++) {
        int c0 = cb + kh * 8;
        uint4 l0 = *(const uint4*)(lut + c0);
        uint4 l1 = *(const uint4*)(lut + c0 + 4);
        uint32_t hp[4];
        hp[0] = cvth2(xb[l0.x >> 16] * hb[l0.x & 0xffffu], xb[l0.y >> 16] * hb[l0.y & 0xffffu]);
        hp[1] = cvth2(xb[l0.z >> 16] * hb[l0.z & 0xffffu], xb[l0.w >> 16] * hb[l0.w & 0xffffu]);
        hp[2] = cvth2(xb[l1.x >> 16] * hb[l1.x & 0xffffu], xb[l1.y >> 16] * hb[l1.y & 0xffffu]);
        hp[3] = cvth2(xb[l1.z >> 16] * hb[l1.z & 0xffffu], xb[l1.w >> 16] * hb[l1.w & 0xffffu]);
        *(uint4*)(abuf + base + kh * 128) = *(uint4*)hp;
    }
}

template <int NF, int LMODE>
__device__ void run_layer(const unsigned char* img, int T2, int K,
                          const float* xs, const float* hsrc, float* hs,
                          const float* bias, float* out,
                          char* smem, uint32_t sb, int bbase, int Btot)
{
    const int tid = threadIdx.x;
    const int w = tid >> 5, lane = tid & 31;
    const int mq = w >> 1, nh = w & 1;       // mq 0..5 (batch/m32), nh 0..1

    // stageA thread mapping
    const int sA = (tid >= 192) ? 1 : 0;
    const int rA = tid - sA * 192;
    const float* xbA = xs + (rA >> 5) * F0C * DD + (rA & 31);
    const float* hbA = hsrc + (rA >> 5) * NF * DD + (rA & 31);

    // build index LUT (padding c>=K -> offset 0; W image is zero there)
    uint32_t* lut = (uint32_t*)(smem + SM_LUT);
    for (int c = tid; c < T2 * 32; c += NT) {
        int m = 0, n = 0;
        if (c < K) { m = c / NF; n = c - m * NF; }
        lut[c] = ((uint32_t)(m * DD) << 16) | (uint32_t)(n * DD);
    }

    float acc[2][13][4];
#pragma unroll
    for (int mt = 0; mt < 2; mt++)
#pragma unroll
        for (int nt = 0; nt < 13; nt++)
#pragma unroll
            for (int q = 0; q < 4; q++) acc[mt][nt][q] = 0.f;

    prefetchB(img, 0, T2, sb, tid);
    prefetchB(img, 1, T2, sb, tid);
    prefetchB(img, 2, T2, sb, tid);
    __syncthreads();                    // lut + hsrc visible
    stageA<NF>(0, lut, xbA, hbA, smem + SM_A, rA, sA);

    const uint32_t aoff = ((lane >> 3) & 1) * 256u + (lane >> 4) * 128u + (lane & 7) * 16u;
    const uint32_t boff = (uint32_t)lane * 16u;
    const uint32_t boff2 = (uint32_t)(lane & 15) * 16u;

    for (int t = 0; t < T2; t++) {
        cp_wait<2>();
        __syncthreads();
        prefetchB(img, t + 3, T2, sb, tid);

        uint32_t ab = sb + SM_A + (uint32_t)(t & 1) * ABUF32 + (uint32_t)mq * 1024u;
        uint32_t bbase2 = sb + SM_B + (uint32_t)(t & 3) * (uint32_t)BBLK32 + (uint32_t)nh * 3328u;
#pragma unroll
        for (int s = 0; s < 2; s++) {
            uint32_t ah[2][4];
            ldsm4(ah[0], ab + (uint32_t)s * 6144u + aoff);
            ldsm4(ah[1], ab + (uint32_t)s * 6144u + 512u + aoff);
            uint32_t bb = bbase2 + (uint32_t)s * (uint32_t)BBLK16;
#pragma unroll
            for (int i = 0; i < 6; i++) {
                uint32_t bh[4];
                ldsm4(bh, bb + i * 512u + boff);
                MMA(acc[0][2 * i], ah[0], bh[0], bh[1]);
                MMA(acc[1][2 * i], ah[1], bh[0], bh[1]);
                MMA(acc[0][2 * i + 1], ah[0], bh[2], bh[3]);
                MMA(acc[1][2 * i + 1], ah[1], bh[2], bh[3]);
            }
            uint32_t bh2[2];
            ldsm2(bh2, bb + 3072u + boff2);
            MMA(acc[0][12], ah[0], bh2[0], bh2[1]);
            MMA(acc[1][12], ah[1], bh2[0], bh2[1]);
        }
        if (t + 1 < T2)
            stageA<NF>(t + 1, lut, xbA, hbA,
                       smem + SM_A + ((t + 1) & 1) * ABUF32, rA, sA);
    }
    cp_wait<0>();

    // ---- epilogue: warp (mq,nh) owns batch mq, columns nh*104.. fully ----
    int b = bbase + mq;
    bool bok = b < Btot;
    int quad = lane & 3, ldq = lane >> 2;
    const float* bi = bias + LMODE * SS;
    float* outp = out + (size_t)b * (2 * SS);
#pragma unroll
    for (int nt = 0; nt < 13; nt++) {
        int oe = nh * 104 + nt * 8 + 2 * quad;
        float be = bi[oe], bo = bi[oe + 1];
        float se = 0.f, so = 0.f;
#pragma unroll
        for (int mt = 0; mt < 2; mt++) {
            float v0 = fmaxf(acc[mt][nt][0] + be, 0.f);
            float v1 = fmaxf(acc[mt][nt][1] + bo, 0.f);
            float v2 = fmaxf(acc[mt][nt][2] + be, 0.f);
            float v3 = fmaxf(acc[mt][nt][3] + bo, 0.f);
            if (LMODE < 2 && bok) {
                int d0 = mt * 16 + ldq;
                if (oe < NFH) {
                    hs[(mq * NFH + oe) * DD + d0] = v0;
                    hs[(mq * NFH + oe) * DD + d0 + 8] = v2;
                }
                if (oe + 1 < NFH) {
                    hs[(mq * NFH + oe + 1) * DD + d0] = v1;
                    hs[(mq * NFH + oe + 1) * DD + d0 + 8] = v3;
                }
            }
            se += v0 + v2;
            so += v1 + v3;
        }
        se += __shfl_xor_sync(0xffffffffu, se, 4);
        se += __shfl_xor_sync(0xffffffffu, se, 8);
        se += __shfl_xor_sync(0xffffffffu, se, 16);
        so += __shfl_xor_sync(0xffffffffu, so, 4);
        so += __shfl_xor_sync(0xffffffffu, so, 8);
        so += __shfl_xor_sync(0xffffffffu, so, 16);
        if (ldq == 0 && bok) {
            bool de = (LMODE == 2) ? (oe < SS) : (oe >= NFH && oe < SS);
            bool dd = (LMODE == 2) ? (oe + 1 < SS) : (oe + 1 >= NFH && oe + 1 < SS);
            int che = (LMODE == 0) ? (oe - NFH) : (LMODE == 1) ? oe : (SS + oe);
            if (de) outp[che] = se;
            if (dd) outp[che + 1] = so;
        }
    }
    __syncthreads();   // hs complete + A/B bufs free before next layer
}

__global__ void __launch_bounds__(NT, 1)
cin_main(const float* __restrict__ x,
         const float* __restrict__ b0g, const float* __restrict__ b1g,
         const float* __restrict__ b2g,
         float* __restrict__ out, int Btot)
{
    extern __shared__ char smem[];
    uint32_t sb = (uint32_t)__cvta_generic_to_shared(smem);
    int tid = threadIdx.x;

    float* bias = (float*)(smem + SM_BIAS);
    for (int i = tid; i < 3 * SS; i += NT)
        bias[i] = (i < SS) ? b0g[i] : (i < 2 * SS) ? b1g[i - SS] : b2g[i - 2 * SS];

    float* xs = (float*)(smem + SM_X);
    float* hs = (float*)(smem + SM_H);
    int bbase = blockIdx.x * NBATCH;
    for (int bl = 0; bl < NBATCH; bl++) {
        int b = bbase + bl;
        float4* dst = (float4*)(xs + bl * F0C * DD);
        if (b < Btot) {
            const float4* src = (const float4*)(x + (size_t)b * (F0C * DD));
            for (int i = tid; i < F0C * DD / 4; i += NT) dst[i] = src[i];
        } else {
            float4 z = make_float4(0.f, 0.f, 0.f, 0.f);
            for (int i = tid; i < F0C * DD / 4; i += NT) dst[i] = z;
        }
    }
    __syncthreads();

    run_layer<F0C, 0>(g_wimg, T0 / 2, K0, xs, xs, hs, bias, out, smem, sb, bbase, Btot);
    run_layer<NFH, 1>(g_wimg + IMG0_BYTES, T12 / 2, K12, xs, hs, hs, bias, out, smem, sb, bbase, Btot);
    run_layer<NFH, 2>(g_wimg + IMG0_BYTES + IMG12_BYTES, T12 / 2, K12, xs, hs, hs, bias, out, smem, sb, bbase, Btot);
}

extern "C" void kernel_launch(void* const* d_in, const int* in_sizes, int n_in,
                              void* d_out, int out_size)
{
    const float* x = nullptr;
    const float* W0 = nullptr;
    const float* W1 = nullptr;
    const float* W2 = nullptr;
    const float* bb[3] = {nullptr, nullptr, nullptr};
    int nb = 0;
    long xsz = 0;

    for (int i = 0; i < n_in; i++) {
        long sz = in_sizes[i];
        const float* p = (const float*)d_in[i];
        if (sz == (long)K0 * SS) W0 = p;
        else if (sz == (long)K12 * SS) { if (!W1) W1 = p; else W2 = p; }
        else if (sz == SS) { if (nb < 3) bb[nb++] = p; }
        else { x = p; xsz = sz; }
    }

    int B = (int)(xsz / (F0C * DD));

    int n0 = T0 * 8 * NPAD, n12 = T12 * 8 * NPAD;
    prep_kernel<<<(n0 + 255) / 256, 256>>>(W0, K0, T0, 0);
    prep_kernel<<<(n12 + 255) / 256, 256>>>(W1, K12, T12, 1);
    prep_kernel<<<(n12 + 255) / 256, 256>>>(W2, K12, T12, 2);

    cudaFuncSetAttribute(cin_main, cudaFuncAttributeMaxDynamicSharedMemorySize, SMEM_TOTAL);
    cin_main<<<(B + NBATCH - 1) / NBATCH, NT, SMEM_TOTAL>>>(x, bb[0], bb[1], bb[2],
                                                            (float*)d_out, B);
}

// round 9
// speedup vs baseline: 8.6063x; 1.0206x over previous
#include <cuda_runtime.h>
#include <cstdint>

#define F0C 39
#define DD 32
#define SS 200
#define NFH 100
#define NPAD 208
#define K0 1521
#define T0 96          // k16 tiles
#define K12 3900
#define T12 244

#define NBATCH 7                // batches per CTA -> grid 293 = 1.98 waves
#define NT 448                  // 14 warps

#define BBLK16 6656             // one k16 B image
#define BBLK32 13312
#define ABUF16 7168             // 224 rows x 16 k x 2B
#define ABUF32 14336
#define IMG0_BYTES (T0 * BBLK16)
#define IMG12_BYTES (T12 * BBLK16)

#define SM_BIAS 0               // 2400 -> pad 2432
#define SM_X    2432            // 7*39*32*4 = 34944 -> 37376
#define SM_H    37376           // 7*100*32*4 = 89600 -> 126976
#define SM_LUT  126976          // 3904*4 = 15616 -> 142592
#define SM_A    142592          // 2 * 14336 -> 171264
#define SM_B    171264          // 3 * 13312 -> 211200
#define SMEM_TOTAL 211200

__device__ __align__(16) unsigned char g_wimg[IMG0_BYTES + 2 * IMG12_BYTES];

__device__ __forceinline__ void cp_async16(uint32_t s, const void* g) {
    asm volatile("cp.async.cg.shared.global [%0], [%1], 16;\n" :: "r"(s), "l"(g) : "memory");
}
__device__ __forceinline__ void cp_commit() { asm volatile("cp.async.commit_group;\n" ::: "memory"); }
template <int N> __device__ __forceinline__ void cp_wait() {
    asm volatile("cp.async.wait_group %0;\n" :: "n"(N) : "memory");
}
__device__ __forceinline__ uint32_t cvth2(float p0, float p1) {
    uint32_t r;
    asm("cvt.rn.f16x2.f32 %0, %1, %2;" : "=r"(r) : "f"(p1), "f"(p0));
    return r;
}
__device__ __forceinline__ void ldsm4(uint32_t* r, uint32_t a) {
    asm volatile("ldmatrix.sync.aligned.m8n8.x4.shared.b16 {%0,%1,%2,%3}, [%4];"
                 : "=r"(r[0]), "=r"(r[1]), "=r"(r[2]), "=r"(r[3]) : "r"(a));
}
__device__ __forceinline__ void ldsm2(uint32_t* r, uint32_t a) {
    asm volatile("ldmatrix.sync.aligned.m8n8.x2.shared.b16 {%0,%1}, [%2];"
                 : "=r"(r[0]), "=r"(r[1]) : "r"(a));
}
#define MMA(D, A, B0, B1)                                                     \
    asm volatile("mma.sync.aligned.m16n8k16.row.col.f32.f16.f16.f32 "         \
                 "{%0,%1,%2,%3}, {%4,%5,%6,%7}, {%8,%9}, {%0,%1,%2,%3};"      \
                 : "+f"(D[0]), "+f"(D[1]), "+f"(D[2]), "+f"(D[3])             \
                 : "r"((A)[0]), "r"((A)[1]), "r"((A)[2]), "r"((A)[3]),        \
                   "r"(B0), "r"(B1))

// ---- prep: W[K,200] -> tile-packed fp16 images (8x8 mats, n-major rows) ----
__global__ void prep_kernel(const float* __restrict__ W, int K, int T, int which)
{
    unsigned char* img = g_wimg +
        ((which == 0) ? 0 : (which == 1) ? IMG0_BYTES : (IMG0_BYTES + IMG12_BYTES));
    int idx = blockIdx.x * 256 + threadIdx.x;
    if (idx >= T * 8 * NPAD) return;
    int o = idx % NPAD;
    int r = idx / NPAD;
    int p = r & 7, t = r >> 3;
    int c0 = t * 16 + 2 * p;
    float v0 = (o < SS && c0 < K) ? W[(size_t)c0 * SS + o] : 0.f;
    float v1 = (o < SS && c0 + 1 < K) ? W[(size_t)(c0 + 1) * SS + o] : 0.f;
    uint32_t hp = cvth2(v0, v1);
    int nt = o >> 3, nr = o & 7, ks = p >> 2, j = p & 3;
    size_t off = (size_t)t * BBLK16 + (nt * 2 + ks) * 128 + nr * 16 + j * 4;
    *(uint32_t*)(img + off) = hp;
}

// ---- main ----
__device__ __forceinline__ void prefetchB(const unsigned char* img, int t, int T2,
                                          uint32_t sb, int tid)
{
    if (t < T2) {
        int slot = t % 3;
        const unsigned char* src = img + (size_t)t * BBLK32;
        uint32_t dst = sb + SM_B + (uint32_t)slot * (uint32_t)BBLK32;
        for (int i = tid; i < BBLK32 / 16; i += NT)
            cp_async16(dst + 16u * (uint32_t)i, src + 16 * i);
    }
    cp_commit();
}

// Build A (z products) for one k32 block: 224 rows x 32 k.
// Thread (r = tid%224, s = tid/224) handles 16 k of subtile s for row r.
template <int NF>
__device__ __forceinline__ void stageA(int t, const uint32_t* lut,
                                       const float* xb, const float* hb,
                                       char* abuf, int r, int s)
{
    int cb = t * 32 + s * 16;
    uint32_t base = (uint32_t)(s * ABUF16 + (r >> 3) * 256 + (r & 7) * 16);
#pragma unroll
    for (int kh = 0; kh < 2; kh++) {
        int c0 = cb + kh * 8;
        uint4 l0 = *(const uint4*)(lut + c0);
        uint4 l1 = *(const uint4*)(lut + c0 + 4);
        uint32_t hp[4];
        hp[0] = cvth2(xb[l0.x >> 16] * hb[l0.x & 0xffffu], xb[l0.y >> 16] * hb[l0.y & 0xffffu]);
        hp[1] = cvth2(xb[l0.z >> 16] * hb[l0.z & 0xffffu], xb[l0.w >> 16] * hb[l0.w & 0xffffu]);
        hp[2] = cvth2(xb[l1.x >> 16] * hb[l1.x & 0xffffu], xb[l1.y >> 16] * hb[l1.y & 0xffffu]);
        hp[3] = cvth2(xb[l1.z >> 16] * hb[l1.z & 0xffffu], xb[l1.w >> 16] * hb[l1.w & 0xffffu]);
        *(uint4*)(abuf + base + kh * 128) = *(uint4*)hp;
    }
}

template <int NF, int LMODE>
__device__ void run_layer(const unsigned char* img, int T2, int K,
                          const float* xs, const float* hsrc, float* hs,
                          const float* bias, float* out,
                          char* smem, uint32_t sb, int bbase, int Btot)
{
    const int tid = threadIdx.x;
    const int w = tid >> 5, lane = tid & 31;
    const int mq = w >> 1, nh = w & 1;       // mq 0..6 (batch), nh 0..1

    const int sA = (tid >= 224) ? 1 : 0;
    const int rA = tid - sA * 224;
    const float* xbA = xs + (rA >> 5) * F0C * DD + (rA & 31);
    const float* hbA = hsrc + (rA >> 5) * NF * DD + (rA & 31);

    // index LUT (c>=K -> offset 0; W image is zero there, products cancel)
    uint32_t* lut = (uint32_t*)(smem + SM_LUT);
    for (int c = tid; c < T2 * 32; c += NT) {
        int m = 0, n = 0;
        if (c < K) { m = c / NF; n = c - m * NF; }
        lut[c] = ((uint32_t)(m * DD) << 16) | (uint32_t)(n * DD);
    }

    float acc[2][13][4];
#pragma unroll
    for (int mt = 0; mt < 2; mt++)
#pragma unroll
        for (int nt = 0; nt < 13; nt++)
#pragma unroll
            for (int q = 0; q < 4; q++) acc[mt][nt][q] = 0.f;

    prefetchB(img, 0, T2, sb, tid);
    prefetchB(img, 1, T2, sb, tid);
    __syncthreads();                    // lut + hsrc visible
    stageA<NF>(0, lut, xbA, hbA, smem + SM_A, rA, sA);

    const uint32_t aoff = ((lane >> 3) & 1) * 256u + (lane >> 4) * 128u + (lane & 7) * 16u;
    const uint32_t boff = (uint32_t)lane * 16u;
    const uint32_t boff2 = (uint32_t)(lane & 15) * 16u;

    for (int t = 0; t < T2; t++) {
        cp_wait<1>();
        __syncthreads();
        prefetchB(img, t + 2, T2, sb, tid);

        uint32_t ab = sb + SM_A + (uint32_t)(t & 1) * ABUF32 + (uint32_t)mq * 1024u;
        uint32_t bbase2 = sb + SM_B + (uint32_t)(t % 3) * (uint32_t)BBLK32 + (uint32_t)nh * 3328u;
#pragma unroll
        for (int s = 0; s < 2; s++) {
            uint32_t ah[2][4];
            ldsm4(ah[0], ab + (uint32_t)s * (uint32_t)ABUF16 + aoff);
            ldsm4(ah[1], ab + (uint32_t)s * (uint32_t)ABUF16 + 512u + aoff);
            uint32_t bb = bbase2 + (uint32_t)s * (uint32_t)BBLK16;
#pragma unroll
            for (int i = 0; i < 6; i++) {
                uint32_t bh[4];
                ldsm4(bh, bb + i * 512u + boff);
                MMA(acc[0][2 * i], ah[0], bh[0], bh[1]);
                MMA(acc[1][2 * i], ah[1], bh[0], bh[1]);
                MMA(acc[0][2 * i + 1], ah[0], bh[2], bh[3]);
                MMA(acc[1][2 * i + 1], ah[1], bh[2], bh[3]);
            }
            uint32_t bh2[2];
            ldsm2(bh2, bb + 3072u + boff2);
            MMA(acc[0][12], ah[0], bh2[0], bh2[1]);
            MMA(acc[1][12], ah[1], bh2[0], bh2[1]);
        }
        if (t + 1 < T2)
            stageA<NF>(t + 1, lut, xbA, hbA,
                       smem + SM_A + ((t + 1) & 1) * ABUF32, rA, sA);
    }
    cp_wait<0>();

    // ---- epilogue: warp (mq,nh) owns batch mq fully in d ----
    int b = bbase + mq;
    bool bok = b < Btot;
    int quad = lane & 3, ldq = lane >> 2;
    const float* bi = bias + LMODE * SS;
    float* outp = out + (size_t)b * (2 * SS);
#pragma unroll
    for (int nt = 0; nt < 13; nt++) {
        int oe = nh * 104 + nt * 8 + 2 * quad;
        float be = bi[oe], bo = bi[oe + 1];
        float se = 0.f, so = 0.f;
#pragma unroll
        for (int mt = 0; mt < 2; mt++) {
            float v0 = fmaxf(acc[mt][nt][0] + be, 0.f);
            float v1 = fmaxf(acc[mt][nt][1] + bo, 0.f);
            float v2 = fmaxf(acc[mt][nt][2] + be, 0.f);
            float v3 = fmaxf(acc[mt][nt][3] + bo, 0.f);
            if (LMODE < 2 && bok) {
                int d0 = mt * 16 + ldq;
                if (oe < NFH) {
                    hs[(mq * NFH + oe) * DD + d0] = v0;
                    hs[(mq * NFH + oe) * DD + d0 + 8] = v2;
                }
                if (oe + 1 < NFH) {
                    hs[(mq * NFH + oe + 1) * DD + d0] = v1;
                    hs[(mq * NFH + oe + 1) * DD + d0 + 8] = v3;
                }
            }
            se += v0 + v2;
            so += v1 + v3;
        }
        se += __shfl_xor_sync(0xffffffffu, se, 4);
        se += __shfl_xor_sync(0xffffffffu, se, 8);
        se += __shfl_xor_sync(0xffffffffu, se, 16);
        so += __shfl_xor_sync(0xffffffffu, so, 4);
        so += __shfl_xor_sync(0xffffffffu, so, 8);
        so += __shfl_xor_sync(0xffffffffu, so, 16);
        if (ldq == 0 && bok) {
            bool de = (LMODE == 2) ? (oe < SS) : (oe >= NFH && oe < SS);
            bool dd = (LMODE == 2) ? (oe + 1 < SS) : (oe + 1 >= NFH && oe + 1 < SS);
            int che = (LMODE == 0) ? (oe - NFH) : (LMODE == 1) ? oe : (SS + oe);
            if (de) outp[che] = se;
            if (dd) outp[che + 1] = so;
        }
    }
    __syncthreads();   // hs complete + A/B bufs free before next layer
}

__global__ void __launch_bounds__(NT, 1)
cin_main(const float* __restrict__ x,
         const float* __restrict__ b0g, const float* __restrict__ b1g,
         const float* __restrict__ b2g,
         float* __restrict__ out, int Btot)
{
    extern __shared__ char smem[];
    uint32_t sb = (uint32_t)__cvta_generic_to_shared(smem);
    int tid = threadIdx.x;

    float* bias = (float*)(smem + SM_BIAS);
    for (int i = tid; i < 3 * SS; i += NT)
        bias[i] = (i < SS) ? b0g[i] : (i < 2 * SS) ? b1g[i - SS] : b2g[i - 2 * SS];

    float* xs = (float*)(smem + SM_X);
    float* hs = (float*)(smem + SM_H);
    int bbase = blockIdx.x * NBATCH;
    for (int bl = 0; bl < NBATCH; bl++) {
        int b = bbase + bl;
        float4* dst = (float4*)(xs + bl * F0C * DD);
        if (b < Btot) {
            const float4* src = (const float4*)(x + (size_t)b * (F0C * DD));
            for (int i = tid; i < F0C * DD / 4; i += NT) dst[i] = src[i];
        } else {
            float4 z = make_float4(0.f, 0.f, 0.f, 0.f);
            for (int i = tid; i < F0C * DD / 4; i += NT) dst[i] = z;
        }
    }
    __syncthreads();

    run_layer<F0C, 0>(g_wimg, T0 / 2, K0, xs, xs, hs, bias, out, smem, sb, bbase, Btot);
    run_layer<NFH, 1>(g_wimg + IMG0_BYTES, T12 / 2, K12, xs, hs, hs, bias, out, smem, sb, bbase, Btot);
    run_layer<NFH, 2>(g_wimg + IMG0_BYTES + IMG12_BYTES, T12 / 2, K12, xs, hs, hs, bias, out, smem, sb, bbase, Btot);
}

extern "C" void kernel_launch(void* const* d_in, const int* in_sizes, int n_in,
                              void* d_out, int out_size)
{
    const float* x = nullptr;
    const float* W0 = nullptr;
    const float* W1 = nullptr;
    const float* W2 = nullptr;
    const float* bb[3] = {nullptr, nullptr, nullptr};
    int nb = 0;
    long xsz = 0;

    for (int i = 0; i < n_in; i++) {
        long sz = in_sizes[i];
        const float* p = (const float*)d_in[i];
        if (sz == (long)K0 * SS) W0 = p;
        else if (sz == (long)K12 * SS) { if (!W1) W1 = p; else W2 = p; }
        else if (sz == SS) { if (nb < 3) bb[nb++] = p; }
        else { x = p; xsz = sz; }
    }

    int B = (int)(xsz / (F0C * DD));

    int n0 = T0 * 8 * NPAD, n12 = T12 * 8 * NPAD;
    prep_kernel<<<(n0 + 255) / 256, 256>>>(W0, K0, T0, 0);
    prep_kernel<<<(n12 + 255) / 256, 256>>>(W1, K12, T12, 1);
    prep_kernel<<<(n12 + 255) / 256, 256>>>(W2, K12, T12, 2);

    cudaFuncSetAttribute(cin_main, cudaFuncAttributeMaxDynamicSharedMemorySize, SMEM_TOTAL);
    cin_main<<<(B + NBATCH - 1) / NBATCH, NT, SMEM_TOTAL>>>(x, bb[0], bb[1], bb[2],
                                                            (float*)d_out, B);
}

// round 10
// speedup vs baseline: 8.9339x; 1.0381x over previous
#include <cuda_runtime.h>
#include <cstdint>

#define F0C 39
#define DD 32
#define SS 200
#define NFH 100
#define NPAD 208
#define K0 1521
#define T0 96          // k16 tiles
#define K12 3900
#define T12 244

#define NBATCH 7                // batches per CTA -> grid 293 = 1.98 waves
#define NT 448                  // 14 warps

#define BBLK16 6656             // one k16 B image
#define BBLK32 13312
#define ABUF16 7168             // 224 rows x 16 k x 2B
#define ABUF32 14336
#define IMG0_BYTES (T0 * BBLK16)
#define IMG12_BYTES (T12 * BBLK16)

#define SM_BIAS 0               // 2400 -> pad 2432
#define SM_X    2432            // 7*39*32*4 = 34944 -> 37376
#define SM_H    37376           // 7*100*32*4 = 89600 -> 126976
#define SM_LUT  126976          // 3904*4 = 15616 -> 142592
#define SM_A    142592          // 2 * 14336 -> 171264
#define SM_B    171264          // 4 * 13312 -> 224512
#define SMEM_TOTAL 224512

__device__ __align__(16) unsigned char g_wimg[IMG0_BYTES + 2 * IMG12_BYTES];

__device__ __forceinline__ void cp_async16(uint32_t s, const void* g) {
    asm volatile("cp.async.cg.shared.global [%0], [%1], 16;\n" :: "r"(s), "l"(g) : "memory");
}
__device__ __forceinline__ void cp_commit() { asm volatile("cp.async.commit_group;\n" ::: "memory"); }
template <int N> __device__ __forceinline__ void cp_wait() {
    asm volatile("cp.async.wait_group %0;\n" :: "n"(N) : "memory");
}
__device__ __forceinline__ uint32_t cvth2(float p0, float p1) {
    uint32_t r;
    asm("cvt.rn.f16x2.f32 %0, %1, %2;" : "=r"(r) : "f"(p1), "f"(p0));
    return r;
}
__device__ __forceinline__ void ldsm4(uint32_t* r, uint32_t a) {
    asm volatile("ldmatrix.sync.aligned.m8n8.x4.shared.b16 {%0,%1,%2,%3}, [%4];"
                 : "=r"(r[0]), "=r"(r[1]), "=r"(r[2]), "=r"(r[3]) : "r"(a));
}
__device__ __forceinline__ void ldsm2(uint32_t* r, uint32_t a) {
    asm volatile("ldmatrix.sync.aligned.m8n8.x2.shared.b16 {%0,%1}, [%2];"
                 : "=r"(r[0]), "=r"(r[1]) : "r"(a));
}
#define MMA(D, A, B0, B1)                                                     \
    asm volatile("mma.sync.aligned.m16n8k16.row.col.f32.f16.f16.f32 "         \
                 "{%0,%1,%2,%3}, {%4,%5,%6,%7}, {%8,%9}, {%0,%1,%2,%3};"      \
                 : "+f"(D[0]), "+f"(D[1]), "+f"(D[2]), "+f"(D[3])             \
                 : "r"((A)[0]), "r"((A)[1]), "r"((A)[2]), "r"((A)[3]),        \
                   "r"(B0), "r"(B1))

// ---- prep: W[K,200] -> tile-packed fp16 images (8x8 mats, n-major rows) ----
__global__ void prep_kernel(const float* __restrict__ W, int K, int T, int which)
{
    unsigned char* img = g_wimg +
        ((which == 0) ? 0 : (which == 1) ? IMG0_BYTES : (IMG0_BYTES + IMG12_BYTES));
    int idx = blockIdx.x * 256 + threadIdx.x;
    if (idx >= T * 8 * NPAD) return;
    int o = idx % NPAD;
    int r = idx / NPAD;
    int p = r & 7, t = r >> 3;
    int c0 = t * 16 + 2 * p;
    float v0 = (o < SS && c0 < K) ? W[(size_t)c0 * SS + o] : 0.f;
    float v1 = (o < SS && c0 + 1 < K) ? W[(size_t)(c0 + 1) * SS + o] : 0.f;
    uint32_t hp = cvth2(v0, v1);
    int nt = o >> 3, nr = o & 7, ks = p >> 2, j = p & 3;
    size_t off = (size_t)t * BBLK16 + (nt * 2 + ks) * 128 + nr * 16 + j * 4;
    *(uint32_t*)(img + off) = hp;
}

// ---- main ----
__device__ __forceinline__ void prefetchB(const unsigned char* img, int t, int T2,
                                          uint32_t sb, int tid)
{
    if (t < T2) {
        const unsigned char* src = img + (size_t)t * BBLK32;
        uint32_t dst = sb + SM_B + (uint32_t)(t & 3) * (uint32_t)BBLK32;
        for (int i = tid; i < BBLK32 / 16; i += NT)
            cp_async16(dst + 16u * (uint32_t)i, src + 16 * i);
    }
    cp_commit();
}

// Build A (z products) for one k32 block: 224 rows x 32 k.
// Thread (r = tid%224, s = tid/224) handles 16 k of subtile s for row r.
template <int NF>
__device__ __forceinline__ void stageA(int t, const uint32_t* lut,
                                       const float* xb, const float* hb,
                                       char* abuf, int r, int s)
{
    int cb = t * 32 + s * 16;
    uint32_t base = (uint32_t)(s * ABUF16 + (r >> 3) * 256 + (r & 7) * 16);
#pragma unroll
    for (int kh = 0; kh < 2; kh++) {
        int c0 = cb + kh * 8;
        uint4 l0 = *(const uint4*)(lut + c0);
        uint4 l1 = *(const uint4*)(lut + c0 + 4);
        uint32_t hp[4];
        hp[0] = cvth2(xb[l0.x >> 16] * hb[l0.x & 0xffffu], xb[l0.y >> 16] * hb[l0.y & 0xffffu]);
        hp[1] = cvth2(xb[l0.z >> 16] * hb[l0.z & 0xffffu], xb[l0.w >> 16] * hb[l0.w & 0xffffu]);
        hp[2] = cvth2(xb[l1.x >> 16] * hb[l1.x & 0xffffu], xb[l1.y >> 16] * hb[l1.y & 0xffffu]);
        hp[3] = cvth2(xb[l1.z >> 16] * hb[l1.z & 0xffffu], xb[l1.w >> 16] * hb[l1.w & 0xffffu]);
        *(uint4*)(abuf + base + kh * 128) = *(uint4*)hp;
    }
}

template <int NF, int LMODE>
__device__ void run_layer(const unsigned char* img, int T2, int K,
                          const float* xs, const float* hsrc, float* hs,
                          const float* bias, float* out,
                          char* smem, uint32_t sb, int bbase, int Btot)
{
    const int tid = threadIdx.x;
    const int w = tid >> 5, lane = tid & 31;
    const int mq = w >> 1, nh = w & 1;       // mq 0..6 (batch), nh 0..1

    const int sA = (tid >= 224) ? 1 : 0;
    const int rA = tid - sA * 224;
    const float* xbA = xs + (rA >> 5) * F0C * DD + (rA & 31);
    const float* hbA = hsrc + (rA >> 5) * NF * DD + (rA & 31);

    // index LUT (c>=K -> offset 0; W image is zero there, products cancel)
    uint32_t* lut = (uint32_t*)(smem + SM_LUT);
    for (int c = tid; c < T2 * 32; c += NT) {
        int m = 0, n = 0;
        if (c < K) { m = c / NF; n = c - m * NF; }
        lut[c] = ((uint32_t)(m * DD) << 16) | (uint32_t)(n * DD);
    }

    float acc[2][13][4];
#pragma unroll
    for (int mt = 0; mt < 2; mt++)
#pragma unroll
        for (int nt = 0; nt < 13; nt++)
#pragma unroll
            for (int q = 0; q < 4; q++) acc[mt][nt][q] = 0.f;

    prefetchB(img, 0, T2, sb, tid);
    prefetchB(img, 1, T2, sb, tid);
    __syncthreads();                    // lut + hsrc visible
    stageA<NF>(0, lut, xbA, hbA, smem + SM_A, rA, sA);

    const uint32_t aoff = ((lane >> 3) & 1) * 256u + (lane >> 4) * 128u + (lane & 7) * 16u;
    const uint32_t boff = (uint32_t)lane * 16u;
    const uint32_t boff2 = (uint32_t)(lane & 15) * 16u;

    for (int t = 0; t < T2; t++) {
        __syncthreads();   // closes body t-1: A(t) visible, slot (t+2)&3 free

        // independent long-latency work first
        if (t + 1 < T2)
            stageA<NF>(t + 1, lut, xbA, hbA,
                       smem + SM_A + ((t + 1) & 1) * ABUF32, rA, sA);
        prefetchB(img, t + 2, T2, sb, tid);
        cp_wait<2>();      // group t landed; t+1, t+2 still in flight

        uint32_t ab = sb + SM_A + (uint32_t)(t & 1) * ABUF32 + (uint32_t)mq * 1024u;
        uint32_t bbase2 = sb + SM_B + (uint32_t)(t & 3) * (uint32_t)BBLK32 + (uint32_t)nh * 3328u;
#pragma unroll
        for (int s = 0; s < 2; s++) {
            uint32_t ah[2][4];
            ldsm4(ah[0], ab + (uint32_t)s * (uint32_t)ABUF16 + aoff);
            ldsm4(ah[1], ab + (uint32_t)s * (uint32_t)ABUF16 + 512u + aoff);
            uint32_t bb = bbase2 + (uint32_t)s * (uint32_t)BBLK16;
#pragma unroll
            for (int i = 0; i < 6; i++) {
                uint32_t bh[4];
                ldsm4(bh, bb + i * 512u + boff);
                MMA(acc[0][2 * i], ah[0], bh[0], bh[1]);
                MMA(acc[1][2 * i], ah[1], bh[0], bh[1]);
                MMA(acc[0][2 * i + 1], ah[0], bh[2], bh[3]);
                MMA(acc[1][2 * i + 1], ah[1], bh[2], bh[3]);
            }
            uint32_t bh2[2];
            ldsm2(bh2, bb + 3072u + boff2);
            MMA(acc[0][12], ah[0], bh2[0], bh2[1]);
            MMA(acc[1][12], ah[1], bh2[0], bh2[1]);
        }
    }
    cp_wait<0>();

    // ---- epilogue: warp (mq,nh) owns batch mq fully in d ----
    int b = bbase + mq;
    bool bok = b < Btot;
    int quad = lane & 3, ldq = lane >> 2;
    const float* bi = bias + LMODE * SS;
    float* outp = out + (size_t)b * (2 * SS);
#pragma unroll
    for (int nt = 0; nt < 13; nt++) {
        int oe = nh * 104 + nt * 8 + 2 * quad;
        float be = bi[oe], bo = bi[oe + 1];
        float se = 0.f, so = 0.f;
#pragma unroll
        for (int mt = 0; mt < 2; mt++) {
            float v0 = fmaxf(acc[mt][nt][0] + be, 0.f);
            float v1 = fmaxf(acc[mt][nt][1] + bo, 0.f);
            float v2 = fmaxf(acc[mt][nt][2] + be, 0.f);
            float v3 = fmaxf(acc[mt][nt][3] + bo, 0.f);
            if (LMODE < 2 && bok) {
                int d0 = mt * 16 + ldq;
                if (oe < NFH) {
                    hs[(mq * NFH + oe) * DD + d0] = v0;
                    hs[(mq * NFH + oe) * DD + d0 + 8] = v2;
                }
                if (oe + 1 < NFH) {
                    hs[(mq * NFH + oe + 1) * DD + d0] = v1;
                    hs[(mq * NFH + oe + 1) * DD + d0 + 8] = v3;
                }
            }
            se += v0 + v2;
            so += v1 + v3;
        }
        se += __shfl_xor_sync(0xffffffffu, se, 4);
        se += __shfl_xor_sync(0xffffffffu, se, 8);
        se += __shfl_xor_sync(0xffffffffu, se, 16);
        so += __shfl_xor_sync(0xffffffffu, so, 4);
        so += __shfl_xor_sync(0xffffffffu, so, 8);
        so += __shfl_xor_sync(0xffffffffu, so, 16);
        if (ldq == 0 && bok) {
            bool de = (LMODE == 2) ? (oe < SS) : (oe >= NFH && oe < SS);
            bool dd = (LMODE == 2) ? (oe + 1 < SS) : (oe + 1 >= NFH && oe + 1 < SS);
            int che = (LMODE == 0) ? (oe - NFH) : (LMODE == 1) ? oe : (SS + oe);
            if (de) outp[che] = se;
            if (dd) outp[che + 1] = so;
        }
    }
    __syncthreads();   // hs complete + A/B bufs free before next layer
}

__global__ void __launch_bounds__(NT, 1)
cin_main(const float* __restrict__ x,
         const float* __restrict__ b0g, const float* __restrict__ b1g,
         const float* __restrict__ b2g,
         float* __restrict__ out, int Btot)
{
    extern __shared__ char smem[];
    uint32_t sb = (uint32_t)__cvta_generic_to_shared(smem);
    int tid = threadIdx.x;

    float* bias = (float*)(smem + SM_BIAS);
    for (int i = tid; i < 3 * SS; i += NT)
        bias[i] = (i < SS) ? b0g[i] : (i < 2 * SS) ? b1g[i - SS] : b2g[i - 2 * SS];

    float* xs = (float*)(smem + SM_X);
    float* hs = (float*)(smem + SM_H);
    int bbase = blockIdx.x * NBATCH;
    for (int bl = 0; bl < NBATCH; bl++) {
        int b = bbase + bl;
        float4* dst = (float4*)(xs + bl * F0C * DD);
        if (b < Btot) {
            const float4* src = (const float4*)(x + (size_t)b * (F0C * DD));
            for (int i = tid; i < F0C * DD / 4; i += NT) dst[i] = src[i];
        } else {
            float4 z = make_float4(0.f, 0.f, 0.f, 0.f);
            for (int i = tid; i < F0C * DD / 4; i += NT) dst[i] = z;
        }
    }
    __syncthreads();

    run_layer<F0C, 0>(g_wimg, T0 / 2, K0, xs, xs, hs, bias, out, smem, sb, bbase, Btot);
    run_layer<NFH, 1>(g_wimg + IMG0_BYTES, T12 / 2, K12, xs, hs, hs, bias, out, smem, sb, bbase, Btot);
    run_layer<NFH, 2>(g_wimg + IMG0_BYTES + IMG12_BYTES, T12 / 2, K12, xs, hs, hs, bias, out, smem, sb, bbase, Btot);
}

extern "C" void kernel_launch(void* const* d_in, const int* in_sizes, int n_in,
                              void* d_out, int out_size)
{
    const float* x = nullptr;
    const float* W0 = nullptr;
    const float* W1 = nullptr;
    const float* W2 = nullptr;
    const float* bb[3] = {nullptr, nullptr, nullptr};
    int nb = 0;
    long xsz = 0;

    for (int i = 0; i < n_in; i++) {
        long sz = in_sizes[i];
        const float* p = (const float*)d_in[i];
        if (sz == (long)K0 * SS) W0 = p;
        else if (sz == (long)K12 * SS) { if (!W1) W1 = p; else W2 = p; }
        else if (sz == SS) { if (nb < 3) bb[nb++] = p; }
        else { x = p; xsz = sz; }
    }

    int B = (int)(xsz / (F0C * DD));

    int n0 = T0 * 8 * NPAD, n12 = T12 * 8 * NPAD;
    prep_kernel<<<(n0 + 255) / 256, 256>>>(W0, K0, T0, 0);
    prep_kernel<<<(n12 + 255) / 256, 256>>>(W1, K12, T12, 1);
    prep_kernel<<<(n12 + 255) / 256, 256>>>(W2, K12, T12, 2);

    cudaFuncSetAttribute(cin_main, cudaFuncAttributeMaxDynamicSharedMemorySize, SMEM_TOTAL);
    cin_main<<<(B + NBATCH - 1) / NBATCH, NT, SMEM_TOTAL>>>(x, bb[0], bb[1], bb[2],
                                                            (float*)d_out, B);
}

// round 11
// speedup vs baseline: 11.0290x; 1.2345x over previous
#include <cuda_runtime.h>
#include <cuda_fp16.h>
#include <cstdint>

#define F0C 39
#define DD 32
#define SS 200
#define NFH 100
#define NPAD 208

#define NFP0 40                 // padded n-run, layer 0
#define NFP12 104               // padded n-run, layers 1,2
#define T2_0 49                 // k32 tiles (Kp0=1568)
#define T2_12 127               // k32 tiles (Kp12=4064)
#define T16_0 98
#define T16_12 254

#define NBATCH 7
#define NT 448                  // 14 warps

#define BBLK16 6656
#define BBLK32 13312
#define ABUF16 7168
#define ABUF32 14336
#define IMG0_BYTES (T16_0 * BBLK16)
#define IMG12_BYTES (T16_12 * BBLK16)

#define SM_BIAS 0               // 2400 -> 2432
#define SM_XH   2432            // 7*1248 f16 = 17472 -> 19904 -> pad 19968
#define SM_HT0  19968           // 7*32*40 f16 = 17920 -> 37888
#define SM_HT   37888           // 7*32*104 f16 = 46592 -> 84480
#define SM_LUT  84480           // 508*4 = 2032 -> 86528
#define SM_A    86528           // 2*14336 -> 115200
#define SM_B    115200          // 4*13312 -> 168448
#define SMEM_TOTAL 168448

__device__ __align__(16) unsigned char g_wimg[IMG0_BYTES + 2 * IMG12_BYTES];

__device__ __forceinline__ void cp_async16(uint32_t s, const void* g) {
    asm volatile("cp.async.cg.shared.global [%0], [%1], 16;\n" :: "r"(s), "l"(g) : "memory");
}
__device__ __forceinline__ void cp_commit() { asm volatile("cp.async.commit_group;\n" ::: "memory"); }
template <int N> __device__ __forceinline__ void cp_wait() {
    asm volatile("cp.async.wait_group %0;\n" :: "n"(N) : "memory");
}
__device__ __forceinline__ uint32_t cvth2(float p0, float p1) {
    uint32_t r;
    asm("cvt.rn.f16x2.f32 %0, %1, %2;" : "=r"(r) : "f"(p1), "f"(p0));
    return r;
}
__device__ __forceinline__ void ldsm4(uint32_t* r, uint32_t a) {
    asm volatile("ldmatrix.sync.aligned.m8n8.x4.shared.b16 {%0,%1,%2,%3}, [%4];"
                 : "=r"(r[0]), "=r"(r[1]), "=r"(r[2]), "=r"(r[3]) : "r"(a));
}
__device__ __forceinline__ void ldsm2(uint32_t* r, uint32_t a) {
    asm volatile("ldmatrix.sync.aligned.m8n8.x2.shared.b16 {%0,%1}, [%2];"
                 : "=r"(r[0]), "=r"(r[1]) : "r"(a));
}
#define MMA(D, A, B0, B1)                                                     \
    asm volatile("mma.sync.aligned.m16n8k16.row.col.f32.f16.f16.f32 "         \
                 "{%0,%1,%2,%3}, {%4,%5,%6,%7}, {%8,%9}, {%0,%1,%2,%3};"      \
                 : "+f"(D[0]), "+f"(D[1]), "+f"(D[2]), "+f"(D[3])             \
                 : "r"((A)[0]), "r"((A)[1]), "r"((A)[2]), "r"((A)[3]),        \
                   "r"(B0), "r"(B1))

// ---- prep: W[K,200] -> padded-K tile-packed fp16 images ----
// Padded index c' = m*NFP + j ; valid iff m<39 && j<NF (else 0).
__global__ void prep_kernel(const float* __restrict__ W, int NF, int NFP,
                            int T16, int which)
{
    unsigned char* img = g_wimg +
        ((which == 0) ? 0 : (which == 1) ? IMG0_BYTES : (IMG0_BYTES + IMG12_BYTES));
    int idx = blockIdx.x * 256 + threadIdx.x;
    if (idx >= T16 * 8 * NPAD) return;
    int o = idx % NPAD;
    int r = idx / NPAD;
    int p = r & 7, t = r >> 3;
    int c0 = t * 16 + 2 * p;
    float v[2];
#pragma unroll
    for (int u = 0; u < 2; u++) {
        int c = c0 + u;
        int m = c / NFP, j = c - m * NFP;
        v[u] = (o < SS && m < F0C && j < NF) ? W[(size_t)(m * NF + j) * SS + o] : 0.f;
    }
    uint32_t hp = cvth2(v[0], v[1]);
    int nt = o >> 3, nr = o & 7, ks = p >> 2, jj = p & 3;
    size_t off = (size_t)t * BBLK16 + (nt * 2 + ks) * 128 + nr * 16 + jj * 4;
    *(uint32_t*)(img + off) = hp;
}

// ---- main ----
__device__ __forceinline__ void prefetchB(const unsigned char* img, int t, int T2,
                                          uint32_t sb, int tid)
{
    if (t < T2) {
        const unsigned char* src = img + (size_t)t * BBLK32;
        uint32_t dst = sb + SM_B + (uint32_t)(t & 3) * (uint32_t)BBLK32;
        for (int i = tid; i < BBLK32 / 16; i += NT)
            cp_async16(dst + 16u * (uint32_t)i, src + 16 * i);
    }
    cp_commit();
}

// A products for one k32 block: per thread (rA, sA): 2 octets,
// each = 1 LDS.128 (h, f16) + 1 broadcast x (f16) + 4 HMUL2 + STS.128.
template <int NFP>
__device__ __forceinline__ void stageA(int t, const uint32_t* lut,
                                       const __half* xrow, const __half* hrow,
                                       char* abuf, int rA, int sA)
{
    uint32_t base = (uint32_t)(sA * ABUF16 + (rA >> 3) * 256 + (rA & 7) * 16);
#pragma unroll
    for (int kh = 0; kh < 2; kh++) {
        uint32_t L = lut[t * 4 + sA * 2 + kh];
        uint4 hv = *(const uint4*)(hrow + (L & 0xffffu));
        __half2 xx = __half2half2(xrow[L >> 16]);
        const __half2* h2 = (const __half2*)&hv;
        uint4 ov;
        ((__half2*)&ov)[0] = __hmul2(xx, h2[0]);
        ((__half2*)&ov)[1] = __hmul2(xx, h2[1]);
        ((__half2*)&ov)[2] = __hmul2(xx, h2[2]);
        ((__half2*)&ov)[3] = __hmul2(xx, h2[3]);
        *(uint4*)(abuf + base + (uint32_t)kh * 128u) = ov;
    }
}

template <int NFP, int LMODE>
__device__ void run_layer(const unsigned char* img, int T2,
                          const __half* xsh, const __half* hsrc, __half* hT,
                          const float* bias, float* out,
                          char* smem, uint32_t sb, int bbase, int Btot)
{
    const int tid = threadIdx.x;
    const int w = tid >> 5, lane = tid & 31;
    const int mq = w >> 1, nh = w & 1;

    const int sA = (tid >= 224) ? 1 : 0;
    const int rA = tid - sA * 224;
    const int blA = rA >> 5, dA = rA & 31;
    const __half* xrow = xsh + blA * (F0C * DD) + dA;
    const __half* hrow = hsrc + (blA * DD + dA) * NFP;

    // octet LUT: entry = (m*32)<<16 | j0  (clamped to 0 past valid range)
    uint32_t* lut = (uint32_t*)(smem + SM_LUT);
    for (int o8 = tid; o8 < T2 * 4; o8 += NT) {
        int c0 = o8 * 8;
        int m = c0 / NFP, j0 = c0 - m * NFP;
        if (m >= F0C) { m = 0; j0 = 0; }
        lut[o8] = ((uint32_t)(m * DD) << 16) | (uint32_t)j0;
    }

    float acc[2][13][4];
#pragma unroll
    for (int mt = 0; mt < 2; mt++)
#pragma unroll
        for (int nt = 0; nt < 13; nt++)
#pragma unroll
            for (int q = 0; q < 4; q++) acc[mt][nt][q] = 0.f;

    prefetchB(img, 0, T2, sb, tid);
    prefetchB(img, 1, T2, sb, tid);
    __syncthreads();                    // lut + hsrc visible
    stageA<NFP>(0, lut, xrow, hrow, smem + SM_A, rA, sA);

    const uint32_t aoff = ((lane >> 3) & 1) * 256u + (lane >> 4) * 128u + (lane & 7) * 16u;
    const uint32_t boff = (uint32_t)lane * 16u;
    const uint32_t boff2 = (uint32_t)(lane & 15) * 16u;

    for (int t = 0; t < T2; t++) {
        __syncthreads();   // closes body t-1: A(t) visible, slot (t+2)&3 free

        if (t + 1 < T2)
            stageA<NFP>(t + 1, lut, xrow, hrow,
                        smem + SM_A + ((t + 1) & 1) * ABUF32, rA, sA);
        prefetchB(img, t + 2, T2, sb, tid);
        cp_wait<2>();      // group t landed; t+1, t+2 in flight

        uint32_t ab = sb + SM_A + (uint32_t)(t & 1) * ABUF32 + (uint32_t)mq * 1024u;
        uint32_t bbase2 = sb + SM_B + (uint32_t)(t & 3) * (uint32_t)BBLK32 + (uint32_t)nh * 3328u;
#pragma unroll
        for (int s = 0; s < 2; s++) {
            uint32_t ah[2][4];
            ldsm4(ah[0], ab + (uint32_t)s * (uint32_t)ABUF16 + aoff);
            ldsm4(ah[1], ab + (uint32_t)s * (uint32_t)ABUF16 + 512u + aoff);
            uint32_t bb = bbase2 + (uint32_t)s * (uint32_t)BBLK16;
#pragma unroll
            for (int i = 0; i < 6; i++) {
                uint32_t bh[4];
                ldsm4(bh, bb + i * 512u + boff);
                MMA(acc[0][2 * i], ah[0], bh[0], bh[1]);
                MMA(acc[1][2 * i], ah[1], bh[0], bh[1]);
                MMA(acc[0][2 * i + 1], ah[0], bh[2], bh[3]);
                MMA(acc[1][2 * i + 1], ah[1], bh[2], bh[3]);
            }
            uint32_t bh2[2];
            ldsm2(bh2, bb + 3072u + boff2);
            MMA(acc[0][12], ah[0], bh2[0], bh2[1]);
            MMA(acc[1][12], ah[1], bh2[0], bh2[1]);
        }
    }
    cp_wait<0>();

    // ---- epilogue: warp (mq,nh) owns batch mq fully in d ----
    int b = bbase + mq;
    bool bok = b < Btot;
    int quad = lane & 3, ldq = lane >> 2;
    const float* bi = bias + LMODE * SS;
    float* outp = out + (size_t)b * (2 * SS);
    __half* hTw = hT + (size_t)(mq * DD) * NFP12;
#pragma unroll
    for (int nt = 0; nt < 13; nt++) {
        int oe = nh * 104 + nt * 8 + 2 * quad;
        float be = bi[oe], bo = bi[oe + 1];
        float se = 0.f, so = 0.f;
#pragma unroll
        for (int mt = 0; mt < 2; mt++) {
            float v0 = fmaxf(acc[mt][nt][0] + be, 0.f);
            float v1 = fmaxf(acc[mt][nt][1] + bo, 0.f);
            float v2 = fmaxf(acc[mt][nt][2] + be, 0.f);
            float v3 = fmaxf(acc[mt][nt][3] + bo, 0.f);
            if (LMODE < 2 && bok) {
                int d0 = mt * 16 + ldq;
                if (oe < NFH) {
                    hTw[d0 * NFP12 + oe] = __float2half(v0);
                    hTw[(d0 + 8) * NFP12 + oe] = __float2half(v2);
                }
                if (oe + 1 < NFH) {
                    hTw[d0 * NFP12 + oe + 1] = __float2half(v1);
                    hTw[(d0 + 8) * NFP12 + oe + 1] = __float2half(v3);
                }
            }
            se += v0 + v2;
            so += v1 + v3;
        }
        se += __shfl_xor_sync(0xffffffffu, se, 4);
        se += __shfl_xor_sync(0xffffffffu, se, 8);
        se += __shfl_xor_sync(0xffffffffu, se, 16);
        so += __shfl_xor_sync(0xffffffffu, so, 4);
        so += __shfl_xor_sync(0xffffffffu, so, 8);
        so += __shfl_xor_sync(0xffffffffu, so, 16);
        if (ldq == 0 && bok) {
            bool de = (LMODE == 2) ? (oe < SS) : (oe >= NFH && oe < SS);
            bool dd = (LMODE == 2) ? (oe + 1 < SS) : (oe + 1 >= NFH && oe + 1 < SS);
            int che = (LMODE == 0) ? (oe - NFH) : (LMODE == 1) ? oe : (SS + oe);
            if (de) outp[che] = se;
            if (dd) outp[che + 1] = so;
        }
    }
    __syncthreads();   // hT complete + A/B bufs free before next layer
}

__global__ void __launch_bounds__(NT, 1)
cin_main(const float* __restrict__ x,
         const float* __restrict__ b0g, const float* __restrict__ b1g,
         const float* __restrict__ b2g,
         float* __restrict__ out, int Btot)
{
    extern __shared__ char smem[];
    uint32_t sb = (uint32_t)__cvta_generic_to_shared(smem);
    int tid = threadIdx.x;

    float* bias = (float*)(smem + SM_BIAS);
    for (int i = tid; i < 3 * SS; i += NT)
        bias[i] = (i < SS) ? b0g[i] : (i < 2 * SS) ? b1g[i - SS] : b2g[i - 2 * SS];

    __half* xsh = (__half*)(smem + SM_XH);
    __half* hT0 = (__half*)(smem + SM_HT0);
    __half* hT  = (__half*)(smem + SM_HT);
    int bbase = blockIdx.x * NBATCH;

    // stage x as f16: m-major (xsh) and transposed padded (hT0)
    for (int i = tid; i < NBATCH * F0C * DD; i += NT) {
        int bl = i / (F0C * DD), rem = i - bl * (F0C * DD);
        int n = rem >> 5, d = rem & 31;
        int b = bbase + bl;
        float v = (b < Btot) ? x[(size_t)b * (F0C * DD) + rem] : 0.f;
        __half h = __float2half(v);
        xsh[i] = h;
        hT0[(bl * DD + d) * NFP0 + n] = h;
    }
    for (int i = tid; i < NBATCH * DD; i += NT)
        hT0[i * NFP0 + F0C] = __float2half(0.f);          // pad col 39
    for (int i = tid; i < NBATCH * DD * 4; i += NT) {
        int row = i >> 2, c = NFH + (i & 3);
        hT[row * NFP12 + c] = __float2half(0.f);          // pad cols 100..103
    }
    __syncthreads();

    char* sm = smem;
    run_layer<NFP0, 0>(g_wimg, T2_0, xsh, hT0, hT, bias, out, sm, sb, bbase, Btot);
    run_layer<NFP12, 1>(g_wimg + IMG0_BYTES, T2_12, xsh, hT, hT, bias, out, sm, sb, bbase, Btot);
    run_layer<NFP12, 2>(g_wimg + IMG0_BYTES + IMG12_BYTES, T2_12, xsh, hT, hT, bias, out, sm, sb, bbase, Btot);
}

extern "C" void kernel_launch(void* const* d_in, const int* in_sizes, int n_in,
                              void* d_out, int out_size)
{
    const float* x = nullptr;
    const float* W0 = nullptr;
    const float* W1 = nullptr;
    const float* W2 = nullptr;
    const float* bb[3] = {nullptr, nullptr, nullptr};
    int nb = 0;
    long xsz = 0;

    for (int i = 0; i < n_in; i++) {
        long sz = in_sizes[i];
        const float* p = (const float*)d_in[i];
        if (sz == 1521L * SS) W0 = p;
        else if (sz == 3900L * SS) { if (!W1) W1 = p; else W2 = p; }
        else if (sz == SS) { if (nb < 3) bb[nb++] = p; }
        else { x = p; xsz = sz; }
    }

    int B = (int)(xsz / (F0C * DD));

    int n0 = T16_0 * 8 * NPAD, n12 = T16_12 * 8 * NPAD;
    prep_kernel<<<(n0 + 255) / 256, 256>>>(W0, F0C, NFP0, T16_0, 0);
    prep_kernel<<<(n12 + 255) / 256, 256>>>(W1, NFH, NFP12, T16_12, 1);
    prep_kernel<<<(n12 + 255) / 256, 256>>>(W2, NFH, NFP12, T16_12, 2);

    cudaFuncSetAttribute(cin_main, cudaFuncAttributeMaxDynamicSharedMemorySize, SMEM_TOTAL);
    cin_main<<<(B + NBATCH - 1) / NBATCH, NT, SMEM_TOTAL>>>(x, bb[0], bb[1], bb[2],
                                                            (float*)d_out, B);
}